// round 15
// baseline (speedup 1.0000x reference)
#include <cuda_runtime.h>
#include <math.h>
#include <stdint.h>

// ---------------- problem dims ----------------
#define NLAYER 18
#define HDIM   1024
#define NHEAD  8
#define HEADD  256
#define MLPD   4096
#define BATCH  8
#define SEQ    50
#define PREF   800
#define ADIM   32
#define TTOT   850
#define TPAD   864
#define MTOK   400
#define QKVW   2560    // combined qkv row width: q[0,2048) k[2048,2304) v[2304,2560)

// ---------------- device scratch ----------------
__device__ float g_x[MTOK * HDIM];
__device__ float g_h[MTOK * HDIM];
__device__ float g_temb[BATCH * HDIM];
__device__ float g_t1[BATCH * HDIM];
__device__ float g_tv[BATCH * HDIM];
__device__ float g_adaAll[2 * NLAYER * BATCH * HDIM];
__device__ float g_qkv[MTOK * QKVW];
__device__ float g_sc[BATCH * NHEAD * SEQ * TPAD];
__device__ float g_vt[BATCH * HEADD * TPAD];
__device__ float g_ao[MTOK * NHEAD * HEADD];
__device__ float g_gg[MTOK * MLPD];
__device__ float g_uu[MTOK * MLPD];
__device__ int   g_plen[BATCH];
__device__ float g_biasPref[BATCH * PREF];

// ---------------- bf16 split helpers ----------------
__device__ __forceinline__ void split2(float lo, float hi, uint32_t& hw, uint32_t& lw) {
    asm("cvt.rn.bf16x2.f32 %0, %1, %2;" : "=r"(hw) : "f"(hi), "f"(lo));
    float hlo = __uint_as_float(hw << 16);
    float hhi = __uint_as_float(hw & 0xffff0000u);
    asm("cvt.rn.bf16x2.f32 %0, %1, %2;" : "=r"(lw) : "f"(hi - hhi), "f"(lo - hlo));
}
__device__ __forceinline__ void mma_bf16(
    float c[4], const uint32_t a[4], uint32_t b0, uint32_t b1)
{
    asm volatile(
        "mma.sync.aligned.m16n8k16.row.col.f32.bf16.bf16.f32 "
        "{%0,%1,%2,%3}, {%4,%5,%6,%7}, {%8,%9}, {%0,%1,%2,%3};"
        : "+f"(c[0]), "+f"(c[1]), "+f"(c[2]), "+f"(c[3])
        : "r"(a[0]), "r"(a[1]), "r"(a[2]), "r"(a[3]), "r"(b0), "r"(b1));
}
// fast gelu: tanh via __expf (saturates correctly)
__device__ __forceinline__ float gelu_f(float x) {
    float z = 1.5957691216057308f * (x + 0.044715f * x * x * x);  // 2*0.79788456*arg
    float e = __expf(z);
    float t = 1.f - 2.f / (e + 1.f);   // tanh(z/2·2)=tanh(0.79788·arg·2)/... == tanh(z/2)? no:
    // tanh(y) with y = z/2: t = (e^z - 1)/(e^z + 1) = 1 - 2/(e^z + 1). z = 2y. correct.
    return 0.5f * x * (1.f + t);
}

#define PADA 20
#define PADB 136
#define ABUF (64 * PADA)
#define BBUF (16 * PADB)
#define BBUF2 (128 * PADA)
#define SMEM_GEMM_BYTES ((4 * ABUF + 4 * BBUF) * 4)
#define SMEM_ATTN_BYTES ((4 * ABUF + 4 * BBUF2) * 4)

// ============ split-bf16 (3-term) GEMM core, M64, split-K, double-buffered ============
// epiMode: 0 store, 1 accumulate, 2 gated gelu, 3 atomicAdd.
__device__ __forceinline__ void gemm_core(
    const float* __restrict__ A, const float* __restrict__ W,
    float* __restrict__ C, const float* __restrict__ Cg,
    int M, int NwW, int colBaseW, int Nout, int colBaseC,
    int Kstride, int kBase, int nChunks, int rowBase, int epiMode,
    uint32_t* dyn)
{
    uint32_t* AsH = dyn;
    uint32_t* AsL = dyn + 2 * ABUF;
    uint32_t* BsH = dyn + 4 * ABUF;
    uint32_t* BsL = dyn + 4 * ABUF + 2 * BBUF;

    const int tid  = threadIdx.x;
    const int lane = tid & 31;
    const int warp = tid >> 5;
    const int wm = (warp & 1) << 5;
    const int wn = (warp >> 1) << 5;

    const int aRow = tid >> 3;
    const int aK4  = (tid & 7) << 2;
    const int aKw  = (tid & 7) << 1;
    const int bKw  = tid >> 4;
    const int bN   = (tid & 15) << 3;

    float c[2][4][4];
#pragma unroll
    for (int i = 0; i < 2; i++)
#pragma unroll
        for (int j = 0; j < 4; j++)
#pragma unroll
            for (int r = 0; r < 4; r++) c[i][j][r] = 0.f;

    float4 pa[2], pb[4];
    auto loadg = [&](int k0) {
#pragma unroll
        for (int p = 0; p < 2; p++) {
            int gr = rowBase + aRow + (p << 5);
            pa[p] = make_float4(0.f, 0.f, 0.f, 0.f);
            if (gr < M) pa[p] = *(const float4*)(A + (size_t)gr * Kstride + k0 + aK4);
        }
        const float* br0 = W + (size_t)(k0 + 2 * bKw) * NwW + colBaseW + bN;
        pb[0] = *(const float4*)(br0);
        pb[1] = *(const float4*)(br0 + 4);
        pb[2] = *(const float4*)(br0 + NwW);
        pb[3] = *(const float4*)(br0 + NwW + 4);
    };
    auto storeb = [&](int buf) {
        uint32_t* aH = AsH + buf * ABUF;
        uint32_t* aL = AsL + buf * ABUF;
        uint32_t* bH = BsH + buf * BBUF;
        uint32_t* bL = BsL + buf * BBUF;
#pragma unroll
        for (int p = 0; p < 2; p++) {
            int r = aRow + (p << 5);
            uint32_t h0, l0, h1, l1;
            split2(pa[p].x, pa[p].y, h0, l0);
            split2(pa[p].z, pa[p].w, h1, l1);
            *(uint2*)(&aH[r * PADA + aKw]) = make_uint2(h0, h1);
            *(uint2*)(&aL[r * PADA + aKw]) = make_uint2(l0, l1);
        }
        uint32_t hw[8], lw[8];
        const float* p0 = (const float*)&pb[0];
        const float* p1 = (const float*)&pb[2];
#pragma unroll
        for (int j = 0; j < 8; j++) split2(p0[j], p1[j], hw[j], lw[j]);
        *(uint4*)(&bH[bKw * PADB + bN])     = make_uint4(hw[0], hw[1], hw[2], hw[3]);
        *(uint4*)(&bH[bKw * PADB + bN + 4]) = make_uint4(hw[4], hw[5], hw[6], hw[7]);
        *(uint4*)(&bL[bKw * PADB + bN])     = make_uint4(lw[0], lw[1], lw[2], lw[3]);
        *(uint4*)(&bL[bKw * PADB + bN + 4]) = make_uint4(lw[4], lw[5], lw[6], lw[7]);
    };

    loadg(kBase);
    storeb(0);
    __syncthreads();

    for (int i = 0; i < nChunks; i++) {
        const int cur = i & 1;
        const bool more = (i + 1 < nChunks);
        if (more) loadg(kBase + ((i + 1) << 5));

        uint32_t* aH = AsH + cur * ABUF;
        uint32_t* aL = AsL + cur * ABUF;
        uint32_t* bH = BsH + cur * BBUF;
        uint32_t* bL = BsL + cur * BBUF;
#pragma unroll
        for (int ks = 0; ks < 2; ks++) {
            const int kf = (ks << 3) + (lane & 3);
            uint32_t bh[4][2], bl[4][2];
#pragma unroll
            for (int nf = 0; nf < 4; nf++) {
                int n0 = wn + (nf << 3) + (lane >> 2);
                bh[nf][0] = bH[kf * PADB + n0];
                bh[nf][1] = bH[(kf + 4) * PADB + n0];
                bl[nf][0] = bL[kf * PADB + n0];
                bl[nf][1] = bL[(kf + 4) * PADB + n0];
            }
#pragma unroll
            for (int mf = 0; mf < 2; mf++) {
                int m0 = wm + (mf << 4) + (lane >> 2);
                uint32_t ah[4], al[4];
                ah[0] = aH[m0 * PADA + kf];
                ah[1] = aH[(m0 + 8) * PADA + kf];
                ah[2] = aH[m0 * PADA + kf + 4];
                ah[3] = aH[(m0 + 8) * PADA + kf + 4];
                al[0] = aL[m0 * PADA + kf];
                al[1] = aL[(m0 + 8) * PADA + kf];
                al[2] = aL[m0 * PADA + kf + 4];
                al[3] = aL[(m0 + 8) * PADA + kf + 4];
#pragma unroll
                for (int nf = 0; nf < 4; nf++) {
                    mma_bf16(c[mf][nf], al, bh[nf][0], bh[nf][1]);
                    mma_bf16(c[mf][nf], ah, bl[nf][0], bl[nf][1]);
                    mma_bf16(c[mf][nf], ah, bh[nf][0], bh[nf][1]);
                }
            }
        }
        if (more) storeb(cur ^ 1);
        __syncthreads();
    }

#pragma unroll
    for (int mf = 0; mf < 2; mf++) {
        int r0 = rowBase + wm + (mf << 4) + (lane >> 2);
#pragma unroll
        for (int nf = 0; nf < 4; nf++) {
            int cc = colBaseC + wn + (nf << 3) + ((lane & 3) << 1);
#pragma unroll
            for (int half = 0; half < 2; half++) {
                int rr = r0 + half * 8;
                if (rr >= M) continue;
                size_t off = (size_t)rr * Nout + cc;
                float2 v = make_float2(c[mf][nf][half * 2], c[mf][nf][half * 2 + 1]);
                if (epiMode == 3) {
                    atomicAdd(C + off, v.x);
                    atomicAdd(C + off + 1, v.y);
                    continue;
                }
                if (epiMode == 1) {
                    float2 old = *(float2*)(C + off);
                    v.x += old.x; v.y += old.y;
                } else if (epiMode == 2) {
                    float2 gg = *(const float2*)(Cg + off);
                    v.x *= gelu_f(gg.x); v.y *= gelu_f(gg.y);
                }
                *(float2*)(C + off) = v;
            }
        }
    }
}

__global__ void __launch_bounds__(256, 2) mma_gemm_kernel(
    const float* __restrict__ A, const float* __restrict__ W,
    float* __restrict__ C, const float* __restrict__ Cg,
    int M, int N, int K, int epiMode)
{
    extern __shared__ uint32_t dyn[];
    int splits = gridDim.z;
    int kLen = K / splits;
    int kBase = blockIdx.z * kLen;
    int em = (splits > 1) ? 3 : epiMode;
    gemm_core(A, W, C, Cg, M, N, blockIdx.x * 128, N, blockIdx.x * 128,
              K, kBase, kLen >> 5, blockIdx.y * 64, em, dyn);
}

// fused QKV into combined buffer: grid (20, 7, 2) split-K, atomicAdd into zeroed output
__global__ void __launch_bounds__(256, 2) qkv_kernel(
    const float* __restrict__ A,
    const float* __restrict__ Wq, const float* __restrict__ Wk, const float* __restrict__ Wv,
    float* __restrict__ qkv)
{
    extern __shared__ uint32_t dyn[];
    int bx = blockIdx.x;
    const float* W; int NwW, colBaseW, colBaseC;
    if (bx < 16)      { W = Wq; NwW = 2048; colBaseW = bx * 128;        colBaseC = bx * 128; }
    else if (bx < 18) { W = Wk; NwW = 256;  colBaseW = (bx - 16) * 128; colBaseC = 2048 + (bx - 16) * 128; }
    else              { W = Wv; NwW = 256;  colBaseW = (bx - 18) * 128; colBaseC = 2304 + (bx - 18) * 128; }
    int kBase = blockIdx.z << 9;
    gemm_core(A, W, qkv, nullptr, MTOK, NwW, colBaseW, QKVW, colBaseC,
              HDIM, kBase, 16, blockIdx.y * 64, 3, dyn);
}

// ============ attention scores, double-buffered ============
// grid (7, 7, 8). S = Q @ K^T / 16 + bias.
__global__ void __launch_bounds__(256, 2) attn_scores_kernel(
    const float* __restrict__ qkv, const float* __restrict__ kvc, int layer)
{
    extern __shared__ uint32_t dyn[];
    uint32_t* AsH = dyn;
    uint32_t* AsL = dyn + 2 * ABUF;
    uint32_t* BsH = dyn + 4 * ABUF;
    uint32_t* BsL = dyn + 4 * ABUF + 2 * BBUF2;

    const int tid  = threadIdx.x;
    const int lane = tid & 31;
    const int warp = tid >> 5;
    const int wm = (warp & 1) << 5;
    const int wn = (warp >> 1) << 5;
    const int b = blockIdx.z;
    const int rowBase = blockIdx.y * 64;
    const int colBase = blockIdx.x * 128;

    const float* Kc = kvc + ((size_t)(layer * 2) * BATCH + b) * (size_t)(PREF * HEADD);
    const float* Qb = qkv + (size_t)b * SEQ * QKVW;

    const int aRow = tid >> 3;
    const int aK4  = (tid & 7) << 2;
    const int aKw  = (tid & 7) << 1;

    float c[2][4][4];
#pragma unroll
    for (int i = 0; i < 2; i++)
#pragma unroll
        for (int j = 0; j < 4; j++)
#pragma unroll
            for (int r = 0; r < 4; r++) c[i][j][r] = 0.f;

    float4 pa[2], pb[4];
    auto loadg = [&](int k0) {
#pragma unroll
        for (int p = 0; p < 2; p++) {
            int gr = rowBase + aRow + (p << 5);
            pa[p] = make_float4(0.f, 0.f, 0.f, 0.f);
            if (gr < 400) {
                int s = gr >> 3, h = gr & 7;
                pa[p] = *(const float4*)(Qb + (size_t)s * QKVW + h * 256 + k0 + aK4);
            }
        }
#pragma unroll
        for (int p = 0; p < 4; p++) {
            int t = colBase + aRow + (p << 5);
            pb[p] = make_float4(0.f, 0.f, 0.f, 0.f);
            if (t < PREF)      pb[p] = *(const float4*)(Kc + (size_t)t * 256 + k0 + aK4);
            else if (t < TTOT) pb[p] = *(const float4*)(qkv + (size_t)(b * SEQ + t - PREF) * QKVW + 2048 + k0 + aK4);
        }
    };
    auto storeb = [&](int buf) {
        uint32_t* aH = AsH + buf * ABUF;
        uint32_t* aL = AsL + buf * ABUF;
        uint32_t* bH = BsH + buf * BBUF2;
        uint32_t* bL = BsL + buf * BBUF2;
#pragma unroll
        for (int p = 0; p < 2; p++) {
            int r = aRow + (p << 5);
            uint32_t h0, l0, h1, l1;
            split2(pa[p].x, pa[p].y, h0, l0);
            split2(pa[p].z, pa[p].w, h1, l1);
            *(uint2*)(&aH[r * PADA + aKw]) = make_uint2(h0, h1);
            *(uint2*)(&aL[r * PADA + aKw]) = make_uint2(l0, l1);
        }
#pragma unroll
        for (int p = 0; p < 4; p++) {
            int r = aRow + (p << 5);
            uint32_t h0, l0, h1, l1;
            split2(pb[p].x, pb[p].y, h0, l0);
            split2(pb[p].z, pb[p].w, h1, l1);
            *(uint2*)(&bH[r * PADA + aKw]) = make_uint2(h0, h1);
            *(uint2*)(&bL[r * PADA + aKw]) = make_uint2(l0, l1);
        }
    };

    loadg(0);
    storeb(0);
    __syncthreads();

    for (int i = 0; i < 8; i++) {
        const int cur = i & 1;
        const bool more = (i + 1 < 8);
        if (more) loadg((i + 1) << 5);

        uint32_t* aH = AsH + cur * ABUF;
        uint32_t* aL = AsL + cur * ABUF;
        uint32_t* bH = BsH + cur * BBUF2;
        uint32_t* bL = BsL + cur * BBUF2;
#pragma unroll
        for (int ks = 0; ks < 2; ks++) {
            const int kf = (ks << 3) + (lane & 3);
            uint32_t bh[4][2], bl[4][2];
#pragma unroll
            for (int nf = 0; nf < 4; nf++) {
                int n0 = wn + (nf << 3) + (lane >> 2);
                bh[nf][0] = bH[n0 * PADA + kf];
                bh[nf][1] = bH[n0 * PADA + kf + 4];
                bl[nf][0] = bL[n0 * PADA + kf];
                bl[nf][1] = bL[n0 * PADA + kf + 4];
            }
#pragma unroll
            for (int mf = 0; mf < 2; mf++) {
                int m0 = wm + (mf << 4) + (lane >> 2);
                uint32_t ah[4], al[4];
                ah[0] = aH[m0 * PADA + kf];
                ah[1] = aH[(m0 + 8) * PADA + kf];
                ah[2] = aH[m0 * PADA + kf + 4];
                ah[3] = aH[(m0 + 8) * PADA + kf + 4];
                al[0] = aL[m0 * PADA + kf];
                al[1] = aL[(m0 + 8) * PADA + kf];
                al[2] = aL[m0 * PADA + kf + 4];
                al[3] = aL[(m0 + 8) * PADA + kf + 4];
#pragma unroll
                for (int nf = 0; nf < 4; nf++) {
                    mma_bf16(c[mf][nf], al, bh[nf][0], bh[nf][1]);
                    mma_bf16(c[mf][nf], ah, bl[nf][0], bl[nf][1]);
                    mma_bf16(c[mf][nf], ah, bh[nf][0], bh[nf][1]);
                }
            }
        }
        if (more) storeb(cur ^ 1);
        __syncthreads();
    }

    const float scale = 0.0625f;
#pragma unroll
    for (int mf = 0; mf < 2; mf++) {
        int r0 = rowBase + wm + (mf << 4) + (lane >> 2);
#pragma unroll
        for (int nf = 0; nf < 4; nf++) {
            int t = colBase + wn + (nf << 3) + ((lane & 3) << 1);
            if (t >= TTOT) continue;
            float2 bias;
            bias.x = (t < PREF) ? g_biasPref[b * PREF + t] : 0.f;
            bias.y = (t + 1 < PREF) ? g_biasPref[b * PREF + t + 1] : 0.f;
#pragma unroll
            for (int half = 0; half < 2; half++) {
                int rr = r0 + half * 8;
                if (rr >= 400) continue;
                int h = rr & 7, s = rr >> 3;
                size_t off = ((size_t)(b * 8 + h) * SEQ + s) * TPAD + t;
                float2 v = make_float2(c[mf][nf][half * 2] * scale + bias.x,
                                       c[mf][nf][half * 2 + 1] * scale + bias.y);
                *(float2*)(g_sc + off) = v;
            }
        }
    }
}

// ============ attention PV, double-buffered, split-T 2 ============
// grid (2, 7, 16): z = b*2 + half. atomicAdd into zeroed out.
__global__ void __launch_bounds__(256, 2) attn_pv_kernel(
    const float* __restrict__ vt, float* __restrict__ out)
{
    extern __shared__ uint32_t dyn[];
    uint32_t* AsH = dyn;
    uint32_t* AsL = dyn + 2 * ABUF;
    uint32_t* BsH = dyn + 4 * ABUF;
    uint32_t* BsL = dyn + 4 * ABUF + 2 * BBUF2;

    const int tid  = threadIdx.x;
    const int lane = tid & 31;
    const int warp = tid >> 5;
    const int wm = (warp & 1) << 5;
    const int wn = (warp >> 1) << 5;
    const int bz = blockIdx.z;
    const int b = bz >> 1;
    const int zs = bz & 1;
    const int kBase = zs ? 448 : 0;
    const int nChunks = zs ? 13 : 14;
    const int rowBase = blockIdx.y * 64;
    const int colBase = blockIdx.x * 128;

    const float* Ab = g_sc + (size_t)b * 400 * TPAD;
    const float* Bb = vt + (size_t)b * HEADD * TPAD;

    const int aRow = tid >> 3;
    const int aK4  = (tid & 7) << 2;
    const int aKw  = (tid & 7) << 1;

    float c[2][4][4];
#pragma unroll
    for (int i = 0; i < 2; i++)
#pragma unroll
        for (int j = 0; j < 4; j++)
#pragma unroll
            for (int r = 0; r < 4; r++) c[i][j][r] = 0.f;

    float4 pa[2], pb[4];
    auto loadg = [&](int k0) {
#pragma unroll
        for (int p = 0; p < 2; p++) {
            int gr = rowBase + aRow + (p << 5);
            pa[p] = make_float4(0.f, 0.f, 0.f, 0.f);
            if (gr < 400) pa[p] = *(const float4*)(Ab + (size_t)gr * TPAD + k0 + aK4);
        }
#pragma unroll
        for (int p = 0; p < 4; p++) {
            int d = colBase + aRow + (p << 5);
            pb[p] = *(const float4*)(Bb + (size_t)d * TPAD + k0 + aK4);
        }
    };
    auto storeb = [&](int buf) {
        uint32_t* aH = AsH + buf * ABUF;
        uint32_t* aL = AsL + buf * ABUF;
        uint32_t* bH = BsH + buf * BBUF2;
        uint32_t* bL = BsL + buf * BBUF2;
#pragma unroll
        for (int p = 0; p < 2; p++) {
            int r = aRow + (p << 5);
            uint32_t h0, l0, h1, l1;
            split2(pa[p].x, pa[p].y, h0, l0);
            split2(pa[p].z, pa[p].w, h1, l1);
            *(uint2*)(&aH[r * PADA + aKw]) = make_uint2(h0, h1);
            *(uint2*)(&aL[r * PADA + aKw]) = make_uint2(l0, l1);
        }
#pragma unroll
        for (int p = 0; p < 4; p++) {
            int r = aRow + (p << 5);
            uint32_t h0, l0, h1, l1;
            split2(pb[p].x, pb[p].y, h0, l0);
            split2(pb[p].z, pb[p].w, h1, l1);
            *(uint2*)(&bH[r * PADA + aKw]) = make_uint2(h0, h1);
            *(uint2*)(&bL[r * PADA + aKw]) = make_uint2(l0, l1);
        }
    };

    loadg(kBase);
    storeb(0);
    __syncthreads();

    for (int i = 0; i < nChunks; i++) {
        const int cur = i & 1;
        const bool more = (i + 1 < nChunks);
        if (more) loadg(kBase + ((i + 1) << 5));

        uint32_t* aH = AsH + cur * ABUF;
        uint32_t* aL = AsL + cur * ABUF;
        uint32_t* bH = BsH + cur * BBUF2;
        uint32_t* bL = BsL + cur * BBUF2;
#pragma unroll
        for (int ks = 0; ks < 2; ks++) {
            const int kf = (ks << 3) + (lane & 3);
            uint32_t bh[4][2], bl[4][2];
#pragma unroll
            for (int nf = 0; nf < 4; nf++) {
                int n0 = wn + (nf << 3) + (lane >> 2);
                bh[nf][0] = bH[n0 * PADA + kf];
                bh[nf][1] = bH[n0 * PADA + kf + 4];
                bl[nf][0] = bL[n0 * PADA + kf];
                bl[nf][1] = bL[n0 * PADA + kf + 4];
            }
#pragma unroll
            for (int mf = 0; mf < 2; mf++) {
                int m0 = wm + (mf << 4) + (lane >> 2);
                uint32_t ah[4], al[4];
                ah[0] = aH[m0 * PADA + kf];
                ah[1] = aH[(m0 + 8) * PADA + kf];
                ah[2] = aH[m0 * PADA + kf + 4];
                ah[3] = aH[(m0 + 8) * PADA + kf + 4];
                al[0] = aL[m0 * PADA + kf];
                al[1] = aL[(m0 + 8) * PADA + kf];
                al[2] = aL[m0 * PADA + kf + 4];
                al[3] = aL[(m0 + 8) * PADA + kf + 4];
#pragma unroll
                for (int nf = 0; nf < 4; nf++) {
                    mma_bf16(c[mf][nf], al, bh[nf][0], bh[nf][1]);
                    mma_bf16(c[mf][nf], ah, bl[nf][0], bl[nf][1]);
                    mma_bf16(c[mf][nf], ah, bh[nf][0], bh[nf][1]);
                }
            }
        }
        if (more) storeb(cur ^ 1);
        __syncthreads();
    }

#pragma unroll
    for (int mf = 0; mf < 2; mf++) {
        int r0 = rowBase + wm + (mf << 4) + (lane >> 2);
#pragma unroll
        for (int nf = 0; nf < 4; nf++) {
            int d = colBase + wn + (nf << 3) + ((lane & 3) << 1);
#pragma unroll
            for (int half = 0; half < 2; half++) {
                int rr = r0 + half * 8;
                if (rr >= 400) continue;
                int h = rr / SEQ, s = rr % SEQ;
                size_t off = (((size_t)(b * SEQ + s)) * 8 + h) * 256 + d;
                atomicAdd(out + off,     c[mf][nf][half * 2]);
                atomicAdd(out + off + 1, c[mf][nf][half * 2 + 1]);
            }
        }
    }
}

// ---------------- fused rope (q,k) + V transpose ----------------
__global__ void ropevtrans_kernel(float* __restrict__ qkv,
                                  const float* __restrict__ kvc, int layer,
                                  float* __restrict__ vt)
{
    int bid = blockIdx.x;
    int tid = threadIdx.x;
    if (bid < 1728) {
        __shared__ float tile[32][33];
        int t0 = (bid % 27) * 32;
        int rest = bid / 27;
        int d0 = (rest & 7) * 32;
        int b = rest >> 3;
        int tx = tid & 31, ty = tid >> 5;
        const float* Vc = kvc + ((size_t)(layer * 2 + 1) * BATCH + b) * (size_t)(PREF * HEADD);
#pragma unroll
        for (int j = 0; j < 4; j++) {
            int t = t0 + ty + j * 8;
            float v = 0.f;
            if (t < PREF)      v = Vc[(size_t)t * 256 + d0 + tx];
            else if (t < TTOT) v = qkv[(size_t)(b * SEQ + t - PREF) * QKVW + 2304 + d0 + tx];
            tile[ty + j * 8][tx] = v;
        }
        __syncthreads();
#pragma unroll
        for (int j = 0; j < 4; j++) {
            int d = d0 + ty + j * 8;
            vt[((size_t)b * HEADD + d) * TPAD + t0 + tx] = tile[tx][ty + j * 8];
        }
    } else {
        int idx = (bid - 1728) * 256 + tid;
        if (idx >= MTOK * 9 * 128) return;
        int j = idx & 127;
        int rest = idx >> 7;
        int hh = rest % 9;
        int row = rest / 9;
        int b = row / SEQ, s = row % SEQ;
        float pos = (float)(g_plen[b] + s);
        // 10000^{-j/128} = exp(-j * ln(10000)/128)
        float inv = __expf(-0.071955925f * (float)j);
        float fr = pos * inv;
        float sn, cs;
        __sincosf(fr, &sn, &cs);
        float* p = qkv + (size_t)row * QKVW + ((hh < 8) ? hh * 256 : 2048);
        float x1 = p[j], x2 = p[j + 128];
        p[j]       = x1 * cs - x2 * sn;
        p[j + 128] = x2 * cs + x1 * sn;
    }
}

// ---------------- prep ----------------
__global__ void prep_kernel(const void* __restrict__ maskp,
                            const float* __restrict__ ts)
{
    int bb = blockIdx.x;
    if (bb < BATCH) {
        int b = bb;
        const int* mi = (const int*)maskp;
        const unsigned char* mu = (const unsigned char*)maskp;
        int w0 = mi[0];
        bool is_i32 = (w0 == 0 || w0 == 1);
        __shared__ int cnt;
        if (threadIdx.x == 0) cnt = 0;
        __syncthreads();
        int local = 0;
        for (int t = threadIdx.x; t < PREF; t += blockDim.x) {
            int m = is_i32 ? mi[b * PREF + t] : (int)mu[b * PREF + t];
            bool on = (m != 0);
            g_biasPref[b * PREF + t] = on ? 0.f : -1e9f;
            if (on) local++;
        }
        atomicAdd(&cnt, local);
        __syncthreads();
        if (threadIdx.x == 0) g_plen[b] = cnt;
    } else {
        int b = bb - BATCH;
        float tsb = ts[b];
        for (int i = threadIdx.x; i < 512; i += blockDim.x) {
            float frac = (float)i / 511.f;
            float period = 4e-3f * powf(1000.f, frac);
            float arg = (6.283185307179586f / period) * tsb;
            float sv, cv;
            sincosf(arg, &sv, &cv);
            g_temb[b * HDIM + i]       = sv;
            g_temb[b * HDIM + 512 + i] = cv;
        }
    }
}

// ---------------- SIMT SGEMM (small GEMMs only) ----------------
__global__ void __launch_bounds__(256) sgemm_kernel(
    const float* __restrict__ A, const float* __restrict__ W,
    float* __restrict__ C, const float* __restrict__ bias,
    int M, int N, int K, int lda, int accumulate)
{
    __shared__ float As[16][64];
    __shared__ float Bs[16][64];
    const int tid = threadIdx.x;
    const int tx = tid & 15;
    const int ty = tid >> 4;
    const int rowBase = blockIdx.y * 64;
    const int colBase = blockIdx.x * 64;

    const int lm  = tid >> 2;
    const int lk  = (tid & 3) << 2;
    const int lkr = tid >> 4;
    const int ln  = (tid & 15) << 2;

    float acc[4][4];
#pragma unroll
    for (int i = 0; i < 4; i++)
#pragma unroll
        for (int j = 0; j < 4; j++) acc[i][j] = 0.f;

    for (int k0 = 0; k0 < K; k0 += 16) {
        float4 av = make_float4(0.f, 0.f, 0.f, 0.f);
        int ar = rowBase + lm;
        if (ar < M) av = *(const float4*)(A + (size_t)ar * lda + (k0 + lk));
        As[lk + 0][lm] = av.x;
        As[lk + 1][lm] = av.y;
        As[lk + 2][lm] = av.z;
        As[lk + 3][lm] = av.w;

        float4 bv;
        int bn = colBase + ln;
        const float* wrow = W + (size_t)(k0 + lkr) * N;
        if (bn + 3 < N) {
            bv = *(const float4*)(wrow + bn);
        } else {
            bv.x = (bn + 0 < N) ? wrow[bn + 0] : 0.f;
            bv.y = (bn + 1 < N) ? wrow[bn + 1] : 0.f;
            bv.z = (bn + 2 < N) ? wrow[bn + 2] : 0.f;
            bv.w = (bn + 3 < N) ? wrow[bn + 3] : 0.f;
        }
        *(float4*)(&Bs[lkr][ln]) = bv;
        __syncthreads();

#pragma unroll
        for (int kk = 0; kk < 16; kk++) {
            float4 a = *(const float4*)(&As[kk][ty << 2]);
            float4 b = *(const float4*)(&Bs[kk][tx << 2]);
            acc[0][0] += a.x * b.x; acc[0][1] += a.x * b.y; acc[0][2] += a.x * b.z; acc[0][3] += a.x * b.w;
            acc[1][0] += a.y * b.x; acc[1][1] += a.y * b.y; acc[1][2] += a.y * b.z; acc[1][3] += a.y * b.w;
            acc[2][0] += a.z * b.x; acc[2][1] += a.z * b.y; acc[2][2] += a.z * b.z; acc[2][3] += a.z * b.w;
            acc[3][0] += a.w * b.x; acc[3][1] += a.w * b.y; acc[3][2] += a.w * b.z; acc[3][3] += a.w * b.w;
        }
        __syncthreads();
    }

#pragma unroll
    for (int i = 0; i < 4; i++) {
        int r = rowBase + (ty << 2) + i;
        if (r >= M) continue;
#pragma unroll
        for (int j = 0; j < 4; j++) {
            int cx = colBase + (tx << 2) + j;
            if (cx >= N) continue;
            float v = acc[i][j];
            if (bias) v += bias[cx];
            size_t off = (size_t)r * N + cx;
            if (accumulate) v += C[off];
            C[off] = v;
        }
    }
}

// ---------------- small-M (M<=8) GEMM core ----------------
__device__ __forceinline__ void gemv8_core(
    const float* __restrict__ A, const float* __restrict__ W,
    const float* __restrict__ bias, float* __restrict__ C,
    int N, int K, int act, int bx)
{
    __shared__ float a_s[8 * 1024];
    __shared__ float red[4 * 64 * 8];
    int tid = threadIdx.x;
    for (int e = tid; e < 8 * K; e += 256) a_s[e] = A[e];
    __syncthreads();

    int nl = tid & 63;
    int n  = bx * 64 + nl;
    int ks = tid >> 6;
    float acc[8];
#pragma unroll
    for (int m = 0; m < 8; m++) acc[m] = 0.f;

    int kc = K >> 2;
    if (n < N) {
        int kbeg = ks * kc;
#pragma unroll 4
        for (int k = 0; k < kc; k++) {
            float w = W[(size_t)(kbeg + k) * N + n];
#pragma unroll
            for (int m = 0; m < 8; m++) acc[m] += a_s[m * K + kbeg + k] * w;
        }
    }
#pragma unroll
    for (int m = 0; m < 8; m++) red[tid * 8 + m] = acc[m];
    __syncthreads();
    if (ks == 0 && n < N) {
#pragma unroll
        for (int m = 0; m < 8; m++) {
            float v = red[(0 * 64 + nl) * 8 + m] + red[(1 * 64 + nl) * 8 + m] +
                      red[(2 * 64 + nl) * 8 + m] + red[(3 * 64 + nl) * 8 + m];
            if (bias) v += bias[n];
            if (act == 1) v = v / (1.f + __expf(-v));
            C[(size_t)m * N + n] = v;
        }
    }
}

__global__ void __launch_bounds__(256) gemv8_kernel(
    const float* __restrict__ A, const float* __restrict__ W,
    const float* __restrict__ bias, float* __restrict__ C,
    int N, int K, int act)
{
    gemv8_core(A, W, bias, C, N, K, act, blockIdx.x);
}

__global__ void __launch_bounds__(256) adaall_kernel(
    const float* __restrict__ tvec,
    const float* __restrict__ Wada1, const float* __restrict__ Wada2,
    float* __restrict__ out)
{
    int li = blockIdx.y;
    const float* W = (li < NLAYER) ? (Wada1 + (size_t)li * HDIM * HDIM)
                                   : (Wada2 + (size_t)(li - NLAYER) * HDIM * HDIM);
    gemv8_core(tvec, W, nullptr, out + (size_t)li * BATCH * HDIM,
               HDIM, HDIM, 0, blockIdx.x);
}

// ---------------- rmsnorm (fp32 out) + optional fused zero of aux buffer ----------------
__global__ void __launch_bounds__(256) rmsnorm_kernel(
    const float* __restrict__ x, const float* __restrict__ w,
    const float* __restrict__ ada, float* __restrict__ out,
    float* __restrict__ zeroBuf, int zeroN)
{
    int row = blockIdx.x;
    int b = row / SEQ;
    const float* xr = x + (size_t)row * HDIM;
    __shared__ float red[256];
    float s = 0.f;
    for (int i = threadIdx.x; i < HDIM; i += 256) {
        float v = xr[i];
        s += v * v;
    }
    red[threadIdx.x] = s;
    __syncthreads();
    for (int st = 128; st > 0; st >>= 1) {
        if (threadIdx.x < st) red[threadIdx.x] += red[threadIdx.x + st];
        __syncthreads();
    }
    float r = rsqrtf(red[0] * (1.f / HDIM) + 1e-6f);
    for (int i = threadIdx.x; i < HDIM; i += 256) {
        float gmul = w[i];
        if (ada) gmul *= (1.f + ada[b * HDIM + i]);
        out[(size_t)row * HDIM + i] = xr[i] * r * gmul;
    }
    if (zeroBuf) {
        float4 z = make_float4(0.f, 0.f, 0.f, 0.f);
        for (int i = threadIdx.x; i < (zeroN >> 2); i += 256)
            *(float4*)(zeroBuf + (size_t)row * zeroN + (i << 2)) = z;
    }
}

// ---------------- softmax (zero-pads [TTOT, TPAD)) + fused zero of pao slice ----------------
__global__ void __launch_bounds__(256) softmax_kernel(float* __restrict__ paoZero)
{
    int row = blockIdx.x;
    float* p = g_sc + (size_t)row * TPAD;
    __shared__ float red[256];
    float mx = -1e30f;
    for (int i = threadIdx.x; i < TTOT; i += 256) mx = fmaxf(mx, p[i]);
    red[threadIdx.x] = mx;
    __syncthreads();
    for (int st = 128; st > 0; st >>= 1) {
        if (threadIdx.x < st) red[threadIdx.x] = fmaxf(red[threadIdx.x], red[threadIdx.x + st]);
        __syncthreads();
    }
    float m = red[0];
    __syncthreads();
    float s = 0.f;
    for (int i = threadIdx.x; i < TTOT; i += 256) {
        float e = __expf(p[i] - m);
        p[i] = e;
        s += e;
    }
    red[threadIdx.x] = s;
    __syncthreads();
    for (int st = 128; st > 0; st >>= 1) {
        if (threadIdx.x < st) red[threadIdx.x] += red[threadIdx.x + st];
        __syncthreads();
    }
    float inv = 1.f / red[0];
    for (int i = threadIdx.x; i < TTOT; i += 256) p[i] *= inv;
    if (threadIdx.x < TPAD - TTOT) p[TTOT + threadIdx.x] = 0.f;
    paoZero[(size_t)row * 256 + threadIdx.x] = 0.f;
}

// ---------------- host ----------------
static inline dim3 gemm_grid(int M, int N) { return dim3((N + 63) / 64, (M + 63) / 64); }

extern "C" void kernel_launch(void* const* d_in, const int* in_sizes, int n_in,
                              void* d_out, int out_size)
{
    const float* x_t      = (const float*)d_in[0];
    const float* timestep = (const float*)d_in[1];
    const void*  mask     = d_in[2];
    const float* kvc      = (const float*)d_in[3];
    const float* Wa_in    = (const float*)d_in[4];
    const float* ba_in    = (const float*)d_in[5];
    const float* Wt_in    = (const float*)d_in[6];
    const float* bt_in    = (const float*)d_in[7];
    const float* Wt_out   = (const float*)d_in[8];
    const float* bt_out   = (const float*)d_in[9];
    const float* Wq       = (const float*)d_in[10];
    const float* Wk       = (const float*)d_in[11];
    const float* Wv       = (const float*)d_in[12];
    const float* Wo       = (const float*)d_in[13];
    const float* Wg       = (const float*)d_in[14];
    const float* Wu       = (const float*)d_in[15];
    const float* Wd       = (const float*)d_in[16];
    const float* n1_w     = (const float*)d_in[17];
    const float* n2_w     = (const float*)d_in[18];
    const float* Wada1    = (const float*)d_in[19];
    const float* Wada2    = (const float*)d_in[20];
    const float* nf_w     = (const float*)d_in[21];
    const float* Wa_out   = (const float*)d_in[22];
    const float* ba_out   = (const float*)d_in[23];

    cudaFuncSetAttribute(mma_gemm_kernel,
                         cudaFuncAttributeMaxDynamicSharedMemorySize, SMEM_GEMM_BYTES);
    cudaFuncSetAttribute(qkv_kernel,
                         cudaFuncAttributeMaxDynamicSharedMemorySize, SMEM_GEMM_BYTES);
    cudaFuncSetAttribute(attn_scores_kernel,
                         cudaFuncAttributeMaxDynamicSharedMemorySize, SMEM_ATTN_BYTES);
    cudaFuncSetAttribute(attn_pv_kernel,
                         cudaFuncAttributeMaxDynamicSharedMemorySize, SMEM_ATTN_BYTES);

    void* p;
    cudaGetSymbolAddress(&p, g_x);      float* px    = (float*)p;
    cudaGetSymbolAddress(&p, g_h);      float* ph    = (float*)p;
    cudaGetSymbolAddress(&p, g_temb);   float* ptemb = (float*)p;
    cudaGetSymbolAddress(&p, g_t1);     float* pt1   = (float*)p;
    cudaGetSymbolAddress(&p, g_tv);     float* ptv   = (float*)p;
    cudaGetSymbolAddress(&p, g_adaAll); float* padaA = (float*)p;
    cudaGetSymbolAddress(&p, g_qkv);    float* pqkv  = (float*)p;
    cudaGetSymbolAddress(&p, g_vt);     float* pvt   = (float*)p;
    cudaGetSymbolAddress(&p, g_ao);     float* pao   = (float*)p;
    cudaGetSymbolAddress(&p, g_gg);     float* pg    = (float*)p;
    cudaGetSymbolAddress(&p, g_uu);     float* pu    = (float*)p;

    prep_kernel<<<16, 512>>>(mask, timestep);

    gemv8_kernel<<<16, 256>>>(ptemb, Wt_in, bt_in, pt1, HDIM, HDIM, 1);
    gemv8_kernel<<<16, 256>>>(pt1, Wt_out, bt_out, ptv, HDIM, HDIM, 1);
    adaall_kernel<<<dim3(16, 2 * NLAYER), 256>>>(ptv, Wada1, Wada2, padaA);

    sgemm_kernel<<<gemm_grid(MTOK, HDIM), 256>>>(x_t, Wa_in, px, ba_in,
                                                 MTOK, HDIM, ADIM, ADIM, 0);

    for (int l = 0; l < NLAYER; l++) {
        const float* wq = Wq + (size_t)l * HDIM * (NHEAD * HEADD);
        const float* wk = Wk + (size_t)l * HDIM * HEADD;
        const float* wv = Wv + (size_t)l * HDIM * HEADD;
        const float* wo = Wo + (size_t)l * (NHEAD * HEADD) * HDIM;
        const float* wg = Wg + (size_t)l * HDIM * MLPD;
        const float* wu = Wu + (size_t)l * HDIM * MLPD;
        const float* wd = Wd + (size_t)l * MLPD * HDIM;
        const float* w1 = n1_w + (size_t)l * HDIM;
        const float* w2 = n2_w + (size_t)l * HDIM;
        const float* ada1 = padaA + (size_t)l * BATCH * HDIM;
        const float* ada2 = padaA + (size_t)(NLAYER + l) * BATCH * HDIM;

        // pre-attn norm + fused zero of qkv
        rmsnorm_kernel<<<MTOK, 256>>>(px, w1, ada1, ph, pqkv, QKVW);

        qkv_kernel<<<dim3(20, 7, 2), 256, SMEM_GEMM_BYTES>>>(ph, wq, wk, wv, pqkv);
        ropevtrans_kernel<<<1728 + 1800, 256>>>(pqkv, kvc, l, pvt);

        attn_scores_kernel<<<dim3(7, 7, 8), 256, SMEM_ATTN_BYTES>>>(pqkv, kvc, l);
        softmax_kernel<<<BATCH * NHEAD * SEQ, 256>>>(pao);
        attn_pv_kernel<<<dim3(2, 7, 16), 256, SMEM_ATTN_BYTES>>>(pvt, pao);

        mma_gemm_kernel<<<dim3(8, 7, 4), 256, SMEM_GEMM_BYTES>>>(
            pao, wo, px, nullptr, MTOK, HDIM, NHEAD * HEADD, 1);

        rmsnorm_kernel<<<MTOK, 256>>>(px, w2, ada2, ph, nullptr, 0);

        mma_gemm_kernel<<<dim3(32, 7, 1), 256, SMEM_GEMM_BYTES>>>(
            ph, wg, pg, nullptr, MTOK, MLPD, HDIM, 0);
        mma_gemm_kernel<<<dim3(32, 7, 1), 256, SMEM_GEMM_BYTES>>>(
            ph, wu, pu, pg, MTOK, MLPD, HDIM, 2);
        mma_gemm_kernel<<<dim3(8, 7, 4), 256, SMEM_GEMM_BYTES>>>(
            pu, wd, px, nullptr, MTOK, HDIM, MLPD, 1);
    }

    rmsnorm_kernel<<<MTOK, 256>>>(px, nf_w, nullptr, ph, nullptr, 0);
    sgemm_kernel<<<gemm_grid(MTOK, ADIM), 256>>>(ph, Wa_out, (float*)d_out, ba_out,
                                                 MTOK, ADIM, HDIM, HDIM, 0);
}

// round 16
// speedup vs baseline: 1.0151x; 1.0151x over previous
#include <cuda_runtime.h>
#include <math.h>
#include <stdint.h>

// ---------------- problem dims ----------------
#define NLAYER 18
#define HDIM   1024
#define NHEAD  8
#define HEADD  256
#define MLPD   4096
#define BATCH  8
#define SEQ    50
#define PREF   800
#define ADIM   32
#define TTOT   850
#define TPAD   864
#define MTOK   400
#define QKVW   2560    // combined qkv row width: q[0,2048) k[2048,2304) v[2304,2560)

// ---------------- device scratch ----------------
__device__ float g_x[MTOK * HDIM];
__device__ float g_h[MTOK * HDIM];
__device__ float g_temb[BATCH * HDIM];
__device__ float g_t1[BATCH * HDIM];
__device__ float g_tv[BATCH * HDIM];
__device__ float g_adaAll[2 * NLAYER * BATCH * HDIM];
__device__ float g_qkv[MTOK * QKVW];
__device__ float g_sc[BATCH * NHEAD * SEQ * TPAD];
__device__ float g_vt[BATCH * HEADD * TPAD];
__device__ float g_ao[MTOK * NHEAD * HEADD];
__device__ float g_gg[MTOK * MLPD];
__device__ float g_uu[MTOK * MLPD];
__device__ int   g_plen[BATCH];
__device__ float g_biasPref[BATCH * PREF];

// ---------------- bf16 split helpers ----------------
__device__ __forceinline__ void split2(float lo, float hi, uint32_t& hw, uint32_t& lw) {
    asm("cvt.rn.bf16x2.f32 %0, %1, %2;" : "=r"(hw) : "f"(hi), "f"(lo));
    float hlo = __uint_as_float(hw << 16);
    float hhi = __uint_as_float(hw & 0xffff0000u);
    asm("cvt.rn.bf16x2.f32 %0, %1, %2;" : "=r"(lw) : "f"(hi - hhi), "f"(lo - hlo));
}
__device__ __forceinline__ void mma_bf16(
    float c[4], const uint32_t a[4], uint32_t b0, uint32_t b1)
{
    asm volatile(
        "mma.sync.aligned.m16n8k16.row.col.f32.bf16.bf16.f32 "
        "{%0,%1,%2,%3}, {%4,%5,%6,%7}, {%8,%9}, {%0,%1,%2,%3};"
        : "+f"(c[0]), "+f"(c[1]), "+f"(c[2]), "+f"(c[3])
        : "r"(a[0]), "r"(a[1]), "r"(a[2]), "r"(a[3]), "r"(b0), "r"(b1));
}
__device__ __forceinline__ float gelu_f(float x) {
    float t = tanhf(0.7978845608028654f * (x + 0.044715f * x * x * x));
    return 0.5f * x * (1.f + t);
}

// warp-shuffle block reductions (256 threads)
__device__ __forceinline__ float block_sum256(float v, float* red8) {
#pragma unroll
    for (int o = 16; o > 0; o >>= 1) v += __shfl_xor_sync(0xffffffffu, v, o);
    if ((threadIdx.x & 31) == 0) red8[threadIdx.x >> 5] = v;
    __syncthreads();
    float r = red8[0] + red8[1] + red8[2] + red8[3]
            + red8[4] + red8[5] + red8[6] + red8[7];
    return r;
}
__device__ __forceinline__ float block_max256(float v, float* red8) {
#pragma unroll
    for (int o = 16; o > 0; o >>= 1) v = fmaxf(v, __shfl_xor_sync(0xffffffffu, v, o));
    if ((threadIdx.x & 31) == 0) red8[threadIdx.x >> 5] = v;
    __syncthreads();
    float r = fmaxf(fmaxf(fmaxf(red8[0], red8[1]), fmaxf(red8[2], red8[3])),
                    fmaxf(fmaxf(red8[4], red8[5]), fmaxf(red8[6], red8[7])));
    return r;
}

#define PADA 20
#define PADB 136
#define ABUF (64 * PADA)
#define BBUF (16 * PADB)
#define BBUF2 (128 * PADA)
#define SMEM_GEMM_BYTES ((4 * ABUF + 4 * BBUF) * 4)
#define SMEM_ATTN_BYTES ((4 * ABUF + 4 * BBUF2) * 4)

// ============ split-bf16 (3-term) GEMM core, M64, split-K, double-buffered ============
// epiMode: 0 store, 1 accumulate, 2 gated gelu, 3 atomicAdd.
__device__ __forceinline__ void gemm_core(
    const float* __restrict__ A, const float* __restrict__ W,
    float* __restrict__ C, const float* __restrict__ Cg,
    int M, int NwW, int colBaseW, int Nout, int colBaseC,
    int Kstride, int kBase, int nChunks, int rowBase, int epiMode,
    uint32_t* dyn)
{
    uint32_t* AsH = dyn;
    uint32_t* AsL = dyn + 2 * ABUF;
    uint32_t* BsH = dyn + 4 * ABUF;
    uint32_t* BsL = dyn + 4 * ABUF + 2 * BBUF;

    const int tid  = threadIdx.x;
    const int lane = tid & 31;
    const int warp = tid >> 5;
    const int wm = (warp & 1) << 5;
    const int wn = (warp >> 1) << 5;

    const int aRow = tid >> 3;
    const int aK4  = (tid & 7) << 2;
    const int aKw  = (tid & 7) << 1;
    const int bKw  = tid >> 4;
    const int bN   = (tid & 15) << 3;

    float c[2][4][4];
#pragma unroll
    for (int i = 0; i < 2; i++)
#pragma unroll
        for (int j = 0; j < 4; j++)
#pragma unroll
            for (int r = 0; r < 4; r++) c[i][j][r] = 0.f;

    float4 pa[2], pb[4];
    auto loadg = [&](int k0) {
#pragma unroll
        for (int p = 0; p < 2; p++) {
            int gr = rowBase + aRow + (p << 5);
            pa[p] = make_float4(0.f, 0.f, 0.f, 0.f);
            if (gr < M) pa[p] = *(const float4*)(A + (size_t)gr * Kstride + k0 + aK4);
        }
        const float* br0 = W + (size_t)(k0 + 2 * bKw) * NwW + colBaseW + bN;
        pb[0] = *(const float4*)(br0);
        pb[1] = *(const float4*)(br0 + 4);
        pb[2] = *(const float4*)(br0 + NwW);
        pb[3] = *(const float4*)(br0 + NwW + 4);
    };
    auto storeb = [&](int buf) {
        uint32_t* aH = AsH + buf * ABUF;
        uint32_t* aL = AsL + buf * ABUF;
        uint32_t* bH = BsH + buf * BBUF;
        uint32_t* bL = BsL + buf * BBUF;
#pragma unroll
        for (int p = 0; p < 2; p++) {
            int r = aRow + (p << 5);
            uint32_t h0, l0, h1, l1;
            split2(pa[p].x, pa[p].y, h0, l0);
            split2(pa[p].z, pa[p].w, h1, l1);
            *(uint2*)(&aH[r * PADA + aKw]) = make_uint2(h0, h1);
            *(uint2*)(&aL[r * PADA + aKw]) = make_uint2(l0, l1);
        }
        uint32_t hw[8], lw[8];
        const float* p0 = (const float*)&pb[0];
        const float* p1 = (const float*)&pb[2];
#pragma unroll
        for (int j = 0; j < 8; j++) split2(p0[j], p1[j], hw[j], lw[j]);
        *(uint4*)(&bH[bKw * PADB + bN])     = make_uint4(hw[0], hw[1], hw[2], hw[3]);
        *(uint4*)(&bH[bKw * PADB + bN + 4]) = make_uint4(hw[4], hw[5], hw[6], hw[7]);
        *(uint4*)(&bL[bKw * PADB + bN])     = make_uint4(lw[0], lw[1], lw[2], lw[3]);
        *(uint4*)(&bL[bKw * PADB + bN + 4]) = make_uint4(lw[4], lw[5], lw[6], lw[7]);
    };

    loadg(kBase);
    storeb(0);
    __syncthreads();

    for (int i = 0; i < nChunks; i++) {
        const int cur = i & 1;
        const bool more = (i + 1 < nChunks);
        if (more) loadg(kBase + ((i + 1) << 5));

        uint32_t* aH = AsH + cur * ABUF;
        uint32_t* aL = AsL + cur * ABUF;
        uint32_t* bH = BsH + cur * BBUF;
        uint32_t* bL = BsL + cur * BBUF;
#pragma unroll
        for (int ks = 0; ks < 2; ks++) {
            const int kf = (ks << 3) + (lane & 3);
            uint32_t bh[4][2], bl[4][2];
#pragma unroll
            for (int nf = 0; nf < 4; nf++) {
                int n0 = wn + (nf << 3) + (lane >> 2);
                bh[nf][0] = bH[kf * PADB + n0];
                bh[nf][1] = bH[(kf + 4) * PADB + n0];
                bl[nf][0] = bL[kf * PADB + n0];
                bl[nf][1] = bL[(kf + 4) * PADB + n0];
            }
#pragma unroll
            for (int mf = 0; mf < 2; mf++) {
                int m0 = wm + (mf << 4) + (lane >> 2);
                uint32_t ah[4], al[4];
                ah[0] = aH[m0 * PADA + kf];
                ah[1] = aH[(m0 + 8) * PADA + kf];
                ah[2] = aH[m0 * PADA + kf + 4];
                ah[3] = aH[(m0 + 8) * PADA + kf + 4];
                al[0] = aL[m0 * PADA + kf];
                al[1] = aL[(m0 + 8) * PADA + kf];
                al[2] = aL[m0 * PADA + kf + 4];
                al[3] = aL[(m0 + 8) * PADA + kf + 4];
#pragma unroll
                for (int nf = 0; nf < 4; nf++) {
                    mma_bf16(c[mf][nf], al, bh[nf][0], bh[nf][1]);
                    mma_bf16(c[mf][nf], ah, bl[nf][0], bl[nf][1]);
                    mma_bf16(c[mf][nf], ah, bh[nf][0], bh[nf][1]);
                }
            }
        }
        if (more) storeb(cur ^ 1);
        __syncthreads();
    }

#pragma unroll
    for (int mf = 0; mf < 2; mf++) {
        int r0 = rowBase + wm + (mf << 4) + (lane >> 2);
#pragma unroll
        for (int nf = 0; nf < 4; nf++) {
            int cc = colBaseC + wn + (nf << 3) + ((lane & 3) << 1);
#pragma unroll
            for (int half = 0; half < 2; half++) {
                int rr = r0 + half * 8;
                if (rr >= M) continue;
                size_t off = (size_t)rr * Nout + cc;
                float2 v = make_float2(c[mf][nf][half * 2], c[mf][nf][half * 2 + 1]);
                if (epiMode == 3) {
                    atomicAdd(C + off, v.x);
                    atomicAdd(C + off + 1, v.y);
                    continue;
                }
                if (epiMode == 1) {
                    float2 old = *(float2*)(C + off);
                    v.x += old.x; v.y += old.y;
                } else if (epiMode == 2) {
                    float2 gg = *(const float2*)(Cg + off);
                    v.x *= gelu_f(gg.x); v.y *= gelu_f(gg.y);
                }
                *(float2*)(C + off) = v;
            }
        }
    }
}

__global__ void __launch_bounds__(256, 2) mma_gemm_kernel(
    const float* __restrict__ A, const float* __restrict__ W,
    float* __restrict__ C, const float* __restrict__ Cg,
    int M, int N, int K, int epiMode)
{
    extern __shared__ uint32_t dyn[];
    int splits = gridDim.z;
    int kLen = K / splits;
    int kBase = blockIdx.z * kLen;
    int em = (splits > 1) ? 3 : epiMode;
    gemm_core(A, W, C, Cg, M, N, blockIdx.x * 128, N, blockIdx.x * 128,
              K, kBase, kLen >> 5, blockIdx.y * 64, em, dyn);
}

// fused QKV into combined buffer: grid (20, 7, 2) split-K, atomicAdd into zeroed output
__global__ void __launch_bounds__(256, 2) qkv_kernel(
    const float* __restrict__ A,
    const float* __restrict__ Wq, const float* __restrict__ Wk, const float* __restrict__ Wv,
    float* __restrict__ qkv)
{
    extern __shared__ uint32_t dyn[];
    int bx = blockIdx.x;
    const float* W; int NwW, colBaseW, colBaseC;
    if (bx < 16)      { W = Wq; NwW = 2048; colBaseW = bx * 128;        colBaseC = bx * 128; }
    else if (bx < 18) { W = Wk; NwW = 256;  colBaseW = (bx - 16) * 128; colBaseC = 2048 + (bx - 16) * 128; }
    else              { W = Wv; NwW = 256;  colBaseW = (bx - 18) * 128; colBaseC = 2304 + (bx - 18) * 128; }
    int kBase = blockIdx.z << 9;
    gemm_core(A, W, qkv, nullptr, MTOK, NwW, colBaseW, QKVW, colBaseC,
              HDIM, kBase, 16, blockIdx.y * 64, 3, dyn);
}

// ============ attention scores, double-buffered ============
// grid (7, 7, 8). S = Q @ K^T / 16 + bias.
__global__ void __launch_bounds__(256, 2) attn_scores_kernel(
    const float* __restrict__ qkv, const float* __restrict__ kvc, int layer)
{
    extern __shared__ uint32_t dyn[];
    uint32_t* AsH = dyn;
    uint32_t* AsL = dyn + 2 * ABUF;
    uint32_t* BsH = dyn + 4 * ABUF;
    uint32_t* BsL = dyn + 4 * ABUF + 2 * BBUF2;

    const int tid  = threadIdx.x;
    const int lane = tid & 31;
    const int warp = tid >> 5;
    const int wm = (warp & 1) << 5;
    const int wn = (warp >> 1) << 5;
    const int b = blockIdx.z;
    const int rowBase = blockIdx.y * 64;
    const int colBase = blockIdx.x * 128;

    const float* Kc = kvc + ((size_t)(layer * 2) * BATCH + b) * (size_t)(PREF * HEADD);
    const float* Qb = qkv + (size_t)b * SEQ * QKVW;

    const int aRow = tid >> 3;
    const int aK4  = (tid & 7) << 2;
    const int aKw  = (tid & 7) << 1;

    float c[2][4][4];
#pragma unroll
    for (int i = 0; i < 2; i++)
#pragma unroll
        for (int j = 0; j < 4; j++)
#pragma unroll
            for (int r = 0; r < 4; r++) c[i][j][r] = 0.f;

    float4 pa[2], pb[4];
    auto loadg = [&](int k0) {
#pragma unroll
        for (int p = 0; p < 2; p++) {
            int gr = rowBase + aRow + (p << 5);
            pa[p] = make_float4(0.f, 0.f, 0.f, 0.f);
            if (gr < 400) {
                int s = gr >> 3, h = gr & 7;
                pa[p] = *(const float4*)(Qb + (size_t)s * QKVW + h * 256 + k0 + aK4);
            }
        }
#pragma unroll
        for (int p = 0; p < 4; p++) {
            int t = colBase + aRow + (p << 5);
            pb[p] = make_float4(0.f, 0.f, 0.f, 0.f);
            if (t < PREF)      pb[p] = *(const float4*)(Kc + (size_t)t * 256 + k0 + aK4);
            else if (t < TTOT) pb[p] = *(const float4*)(qkv + (size_t)(b * SEQ + t - PREF) * QKVW + 2048 + k0 + aK4);
        }
    };
    auto storeb = [&](int buf) {
        uint32_t* aH = AsH + buf * ABUF;
        uint32_t* aL = AsL + buf * ABUF;
        uint32_t* bH = BsH + buf * BBUF2;
        uint32_t* bL = BsL + buf * BBUF2;
#pragma unroll
        for (int p = 0; p < 2; p++) {
            int r = aRow + (p << 5);
            uint32_t h0, l0, h1, l1;
            split2(pa[p].x, pa[p].y, h0, l0);
            split2(pa[p].z, pa[p].w, h1, l1);
            *(uint2*)(&aH[r * PADA + aKw]) = make_uint2(h0, h1);
            *(uint2*)(&aL[r * PADA + aKw]) = make_uint2(l0, l1);
        }
#pragma unroll
        for (int p = 0; p < 4; p++) {
            int r = aRow + (p << 5);
            uint32_t h0, l0, h1, l1;
            split2(pb[p].x, pb[p].y, h0, l0);
            split2(pb[p].z, pb[p].w, h1, l1);
            *(uint2*)(&bH[r * PADA + aKw]) = make_uint2(h0, h1);
            *(uint2*)(&bL[r * PADA + aKw]) = make_uint2(l0, l1);
        }
    };

    loadg(0);
    storeb(0);
    __syncthreads();

    for (int i = 0; i < 8; i++) {
        const int cur = i & 1;
        const bool more = (i + 1 < 8);
        if (more) loadg((i + 1) << 5);

        uint32_t* aH = AsH + cur * ABUF;
        uint32_t* aL = AsL + cur * ABUF;
        uint32_t* bH = BsH + cur * BBUF2;
        uint32_t* bL = BsL + cur * BBUF2;
#pragma unroll
        for (int ks = 0; ks < 2; ks++) {
            const int kf = (ks << 3) + (lane & 3);
            uint32_t bh[4][2], bl[4][2];
#pragma unroll
            for (int nf = 0; nf < 4; nf++) {
                int n0 = wn + (nf << 3) + (lane >> 2);
                bh[nf][0] = bH[n0 * PADA + kf];
                bh[nf][1] = bH[n0 * PADA + kf + 4];
                bl[nf][0] = bL[n0 * PADA + kf];
                bl[nf][1] = bL[n0 * PADA + kf + 4];
            }
#pragma unroll
            for (int mf = 0; mf < 2; mf++) {
                int m0 = wm + (mf << 4) + (lane >> 2);
                uint32_t ah[4], al[4];
                ah[0] = aH[m0 * PADA + kf];
                ah[1] = aH[(m0 + 8) * PADA + kf];
                ah[2] = aH[m0 * PADA + kf + 4];
                ah[3] = aH[(m0 + 8) * PADA + kf + 4];
                al[0] = aL[m0 * PADA + kf];
                al[1] = aL[(m0 + 8) * PADA + kf];
                al[2] = aL[m0 * PADA + kf + 4];
                al[3] = aL[(m0 + 8) * PADA + kf + 4];
#pragma unroll
                for (int nf = 0; nf < 4; nf++) {
                    mma_bf16(c[mf][nf], al, bh[nf][0], bh[nf][1]);
                    mma_bf16(c[mf][nf], ah, bl[nf][0], bl[nf][1]);
                    mma_bf16(c[mf][nf], ah, bh[nf][0], bh[nf][1]);
                }
            }
        }
        if (more) storeb(cur ^ 1);
        __syncthreads();
    }

    const float scale = 0.0625f;
#pragma unroll
    for (int mf = 0; mf < 2; mf++) {
        int r0 = rowBase + wm + (mf << 4) + (lane >> 2);
#pragma unroll
        for (int nf = 0; nf < 4; nf++) {
            int t = colBase + wn + (nf << 3) + ((lane & 3) << 1);
            if (t >= TTOT) continue;
            float2 bias;
            bias.x = (t < PREF) ? g_biasPref[b * PREF + t] : 0.f;
            bias.y = (t + 1 < PREF) ? g_biasPref[b * PREF + t + 1] : 0.f;
#pragma unroll
            for (int half = 0; half < 2; half++) {
                int rr = r0 + half * 8;
                if (rr >= 400) continue;
                int h = rr & 7, s = rr >> 3;
                size_t off = ((size_t)(b * 8 + h) * SEQ + s) * TPAD + t;
                float2 v = make_float2(c[mf][nf][half * 2] * scale + bias.x,
                                       c[mf][nf][half * 2 + 1] * scale + bias.y);
                *(float2*)(g_sc + off) = v;
            }
        }
    }
}

// ============ attention PV, double-buffered, split-T 2 ============
// grid (2, 7, 16): z = b*2 + half. atomicAdd into zeroed out.
__global__ void __launch_bounds__(256, 2) attn_pv_kernel(
    const float* __restrict__ vt, float* __restrict__ out)
{
    extern __shared__ uint32_t dyn[];
    uint32_t* AsH = dyn;
    uint32_t* AsL = dyn + 2 * ABUF;
    uint32_t* BsH = dyn + 4 * ABUF;
    uint32_t* BsL = dyn + 4 * ABUF + 2 * BBUF2;

    const int tid  = threadIdx.x;
    const int lane = tid & 31;
    const int warp = tid >> 5;
    const int wm = (warp & 1) << 5;
    const int wn = (warp >> 1) << 5;
    const int bz = blockIdx.z;
    const int b = bz >> 1;
    const int zs = bz & 1;
    const int kBase = zs ? 448 : 0;
    const int nChunks = zs ? 13 : 14;
    const int rowBase = blockIdx.y * 64;
    const int colBase = blockIdx.x * 128;

    const float* Ab = g_sc + (size_t)b * 400 * TPAD;
    const float* Bb = vt + (size_t)b * HEADD * TPAD;

    const int aRow = tid >> 3;
    const int aK4  = (tid & 7) << 2;
    const int aKw  = (tid & 7) << 1;

    float c[2][4][4];
#pragma unroll
    for (int i = 0; i < 2; i++)
#pragma unroll
        for (int j = 0; j < 4; j++)
#pragma unroll
            for (int r = 0; r < 4; r++) c[i][j][r] = 0.f;

    float4 pa[2], pb[4];
    auto loadg = [&](int k0) {
#pragma unroll
        for (int p = 0; p < 2; p++) {
            int gr = rowBase + aRow + (p << 5);
            pa[p] = make_float4(0.f, 0.f, 0.f, 0.f);
            if (gr < 400) pa[p] = *(const float4*)(Ab + (size_t)gr * TPAD + k0 + aK4);
        }
#pragma unroll
        for (int p = 0; p < 4; p++) {
            int d = colBase + aRow + (p << 5);
            pb[p] = *(const float4*)(Bb + (size_t)d * TPAD + k0 + aK4);
        }
    };
    auto storeb = [&](int buf) {
        uint32_t* aH = AsH + buf * ABUF;
        uint32_t* aL = AsL + buf * ABUF;
        uint32_t* bH = BsH + buf * BBUF2;
        uint32_t* bL = BsL + buf * BBUF2;
#pragma unroll
        for (int p = 0; p < 2; p++) {
            int r = aRow + (p << 5);
            uint32_t h0, l0, h1, l1;
            split2(pa[p].x, pa[p].y, h0, l0);
            split2(pa[p].z, pa[p].w, h1, l1);
            *(uint2*)(&aH[r * PADA + aKw]) = make_uint2(h0, h1);
            *(uint2*)(&aL[r * PADA + aKw]) = make_uint2(l0, l1);
        }
#pragma unroll
        for (int p = 0; p < 4; p++) {
            int r = aRow + (p << 5);
            uint32_t h0, l0, h1, l1;
            split2(pb[p].x, pb[p].y, h0, l0);
            split2(pb[p].z, pb[p].w, h1, l1);
            *(uint2*)(&bH[r * PADA + aKw]) = make_uint2(h0, h1);
            *(uint2*)(&bL[r * PADA + aKw]) = make_uint2(l0, l1);
        }
    };

    loadg(kBase);
    storeb(0);
    __syncthreads();

    for (int i = 0; i < nChunks; i++) {
        const int cur = i & 1;
        const bool more = (i + 1 < nChunks);
        if (more) loadg(kBase + ((i + 1) << 5));

        uint32_t* aH = AsH + cur * ABUF;
        uint32_t* aL = AsL + cur * ABUF;
        uint32_t* bH = BsH + cur * BBUF2;
        uint32_t* bL = BsL + cur * BBUF2;
#pragma unroll
        for (int ks = 0; ks < 2; ks++) {
            const int kf = (ks << 3) + (lane & 3);
            uint32_t bh[4][2], bl[4][2];
#pragma unroll
            for (int nf = 0; nf < 4; nf++) {
                int n0 = wn + (nf << 3) + (lane >> 2);
                bh[nf][0] = bH[n0 * PADA + kf];
                bh[nf][1] = bH[n0 * PADA + kf + 4];
                bl[nf][0] = bL[n0 * PADA + kf];
                bl[nf][1] = bL[n0 * PADA + kf + 4];
            }
#pragma unroll
            for (int mf = 0; mf < 2; mf++) {
                int m0 = wm + (mf << 4) + (lane >> 2);
                uint32_t ah[4], al[4];
                ah[0] = aH[m0 * PADA + kf];
                ah[1] = aH[(m0 + 8) * PADA + kf];
                ah[2] = aH[m0 * PADA + kf + 4];
                ah[3] = aH[(m0 + 8) * PADA + kf + 4];
                al[0] = aL[m0 * PADA + kf];
                al[1] = aL[(m0 + 8) * PADA + kf];
                al[2] = aL[m0 * PADA + kf + 4];
                al[3] = aL[(m0 + 8) * PADA + kf + 4];
#pragma unroll
                for (int nf = 0; nf < 4; nf++) {
                    mma_bf16(c[mf][nf], al, bh[nf][0], bh[nf][1]);
                    mma_bf16(c[mf][nf], ah, bl[nf][0], bl[nf][1]);
                    mma_bf16(c[mf][nf], ah, bh[nf][0], bh[nf][1]);
                }
            }
        }
        if (more) storeb(cur ^ 1);
        __syncthreads();
    }

#pragma unroll
    for (int mf = 0; mf < 2; mf++) {
        int r0 = rowBase + wm + (mf << 4) + (lane >> 2);
#pragma unroll
        for (int nf = 0; nf < 4; nf++) {
            int d = colBase + wn + (nf << 3) + ((lane & 3) << 1);
#pragma unroll
            for (int half = 0; half < 2; half++) {
                int rr = r0 + half * 8;
                if (rr >= 400) continue;
                int h = rr / SEQ, s = rr % SEQ;
                size_t off = (((size_t)(b * SEQ + s)) * 8 + h) * 256 + d;
                atomicAdd(out + off,     c[mf][nf][half * 2]);
                atomicAdd(out + off + 1, c[mf][nf][half * 2 + 1]);
            }
        }
    }
}

// ---------------- fused rope (q,k) + V transpose ----------------
__global__ void ropevtrans_kernel(float* __restrict__ qkv,
                                  const float* __restrict__ kvc, int layer,
                                  float* __restrict__ vt)
{
    int bid = blockIdx.x;
    int tid = threadIdx.x;
    if (bid < 1728) {
        __shared__ float tile[32][33];
        int t0 = (bid % 27) * 32;
        int rest = bid / 27;
        int d0 = (rest & 7) * 32;
        int b = rest >> 3;
        int tx = tid & 31, ty = tid >> 5;
        const float* Vc = kvc + ((size_t)(layer * 2 + 1) * BATCH + b) * (size_t)(PREF * HEADD);
#pragma unroll
        for (int j = 0; j < 4; j++) {
            int t = t0 + ty + j * 8;
            float v = 0.f;
            if (t < PREF)      v = Vc[(size_t)t * 256 + d0 + tx];
            else if (t < TTOT) v = qkv[(size_t)(b * SEQ + t - PREF) * QKVW + 2304 + d0 + tx];
            tile[ty + j * 8][tx] = v;
        }
        __syncthreads();
#pragma unroll
        for (int j = 0; j < 4; j++) {
            int d = d0 + ty + j * 8;
            vt[((size_t)b * HEADD + d) * TPAD + t0 + tx] = tile[tx][ty + j * 8];
        }
    } else {
        int idx = (bid - 1728) * 256 + tid;
        if (idx >= MTOK * 9 * 128) return;
        int j = idx & 127;
        int rest = idx >> 7;
        int hh = rest % 9;
        int row = rest / 9;
        int b = row / SEQ, s = row % SEQ;
        float pos = (float)(g_plen[b] + s);
        float inv = powf(10000.f, -(float)j / 128.f);
        float fr = pos * inv;
        float sn, cs;
        sincosf(fr, &sn, &cs);
        float* p = qkv + (size_t)row * QKVW + ((hh < 8) ? hh * 256 : 2048);
        float x1 = p[j], x2 = p[j + 128];
        p[j]       = x1 * cs - x2 * sn;
        p[j + 128] = x2 * cs + x1 * sn;
    }
}

// ---------------- prep ----------------
__global__ void prep_kernel(const void* __restrict__ maskp,
                            const float* __restrict__ ts)
{
    int bb = blockIdx.x;
    if (bb < BATCH) {
        int b = bb;
        const int* mi = (const int*)maskp;
        const unsigned char* mu = (const unsigned char*)maskp;
        int w0 = mi[0];
        bool is_i32 = (w0 == 0 || w0 == 1);
        __shared__ int cnt;
        if (threadIdx.x == 0) cnt = 0;
        __syncthreads();
        int local = 0;
        for (int t = threadIdx.x; t < PREF; t += blockDim.x) {
            int m = is_i32 ? mi[b * PREF + t] : (int)mu[b * PREF + t];
            bool on = (m != 0);
            g_biasPref[b * PREF + t] = on ? 0.f : -1e9f;
            if (on) local++;
        }
        atomicAdd(&cnt, local);
        __syncthreads();
        if (threadIdx.x == 0) g_plen[b] = cnt;
    } else {
        int b = bb - BATCH;
        float tsb = ts[b];
        for (int i = threadIdx.x; i < 512; i += blockDim.x) {
            float frac = (float)i / 511.f;
            float period = 4e-3f * powf(1000.f, frac);
            float arg = (6.283185307179586f / period) * tsb;
            float sv, cv;
            sincosf(arg, &sv, &cv);
            g_temb[b * HDIM + i]       = sv;
            g_temb[b * HDIM + 512 + i] = cv;
        }
    }
}

// ---------------- SIMT SGEMM (small GEMMs only) ----------------
__global__ void __launch_bounds__(256) sgemm_kernel(
    const float* __restrict__ A, const float* __restrict__ W,
    float* __restrict__ C, const float* __restrict__ bias,
    int M, int N, int K, int lda, int accumulate)
{
    __shared__ float As[16][64];
    __shared__ float Bs[16][64];
    const int tid = threadIdx.x;
    const int tx = tid & 15;
    const int ty = tid >> 4;
    const int rowBase = blockIdx.y * 64;
    const int colBase = blockIdx.x * 64;

    const int lm  = tid >> 2;
    const int lk  = (tid & 3) << 2;
    const int lkr = tid >> 4;
    const int ln  = (tid & 15) << 2;

    float acc[4][4];
#pragma unroll
    for (int i = 0; i < 4; i++)
#pragma unroll
        for (int j = 0; j < 4; j++) acc[i][j] = 0.f;

    for (int k0 = 0; k0 < K; k0 += 16) {
        float4 av = make_float4(0.f, 0.f, 0.f, 0.f);
        int ar = rowBase + lm;
        if (ar < M) av = *(const float4*)(A + (size_t)ar * lda + (k0 + lk));
        As[lk + 0][lm] = av.x;
        As[lk + 1][lm] = av.y;
        As[lk + 2][lm] = av.z;
        As[lk + 3][lm] = av.w;

        float4 bv;
        int bn = colBase + ln;
        const float* wrow = W + (size_t)(k0 + lkr) * N;
        if (bn + 3 < N) {
            bv = *(const float4*)(wrow + bn);
        } else {
            bv.x = (bn + 0 < N) ? wrow[bn + 0] : 0.f;
            bv.y = (bn + 1 < N) ? wrow[bn + 1] : 0.f;
            bv.z = (bn + 2 < N) ? wrow[bn + 2] : 0.f;
            bv.w = (bn + 3 < N) ? wrow[bn + 3] : 0.f;
        }
        *(float4*)(&Bs[lkr][ln]) = bv;
        __syncthreads();

#pragma unroll
        for (int kk = 0; kk < 16; kk++) {
            float4 a = *(const float4*)(&As[kk][ty << 2]);
            float4 b = *(const float4*)(&Bs[kk][tx << 2]);
            acc[0][0] += a.x * b.x; acc[0][1] += a.x * b.y; acc[0][2] += a.x * b.z; acc[0][3] += a.x * b.w;
            acc[1][0] += a.y * b.x; acc[1][1] += a.y * b.y; acc[1][2] += a.y * b.z; acc[1][3] += a.y * b.w;
            acc[2][0] += a.z * b.x; acc[2][1] += a.z * b.y; acc[2][2] += a.z * b.z; acc[2][3] += a.z * b.w;
            acc[3][0] += a.w * b.x; acc[3][1] += a.w * b.y; acc[3][2] += a.w * b.z; acc[3][3] += a.w * b.w;
        }
        __syncthreads();
    }

#pragma unroll
    for (int i = 0; i < 4; i++) {
        int r = rowBase + (ty << 2) + i;
        if (r >= M) continue;
#pragma unroll
        for (int j = 0; j < 4; j++) {
            int cx = colBase + (tx << 2) + j;
            if (cx >= N) continue;
            float v = acc[i][j];
            if (bias) v += bias[cx];
            size_t off = (size_t)r * N + cx;
            if (accumulate) v += C[off];
            C[off] = v;
        }
    }
}

// ---------------- small-M (M<=8) GEMM core ----------------
__device__ __forceinline__ void gemv8_core(
    const float* __restrict__ A, const float* __restrict__ W,
    const float* __restrict__ bias, float* __restrict__ C,
    int N, int K, int act, int bx)
{
    __shared__ float a_s[8 * 1024];
    __shared__ float red[4 * 64 * 8];
    int tid = threadIdx.x;
    for (int e = tid; e < 8 * K; e += 256) a_s[e] = A[e];
    __syncthreads();

    int nl = tid & 63;
    int n  = bx * 64 + nl;
    int ks = tid >> 6;
    float acc[8];
#pragma unroll
    for (int m = 0; m < 8; m++) acc[m] = 0.f;

    int kc = K >> 2;
    if (n < N) {
        int kbeg = ks * kc;
#pragma unroll 4
        for (int k = 0; k < kc; k++) {
            float w = W[(size_t)(kbeg + k) * N + n];
#pragma unroll
            for (int m = 0; m < 8; m++) acc[m] += a_s[m * K + kbeg + k] * w;
        }
    }
#pragma unroll
    for (int m = 0; m < 8; m++) red[tid * 8 + m] = acc[m];
    __syncthreads();
    if (ks == 0 && n < N) {
#pragma unroll
        for (int m = 0; m < 8; m++) {
            float v = red[(0 * 64 + nl) * 8 + m] + red[(1 * 64 + nl) * 8 + m] +
                      red[(2 * 64 + nl) * 8 + m] + red[(3 * 64 + nl) * 8 + m];
            if (bias) v += bias[n];
            if (act == 1) v = v / (1.f + expf(-v));
            C[(size_t)m * N + n] = v;
        }
    }
}

__global__ void __launch_bounds__(256) gemv8_kernel(
    const float* __restrict__ A, const float* __restrict__ W,
    const float* __restrict__ bias, float* __restrict__ C,
    int N, int K, int act)
{
    gemv8_core(A, W, bias, C, N, K, act, blockIdx.x);
}

__global__ void __launch_bounds__(256) adaall_kernel(
    const float* __restrict__ tvec,
    const float* __restrict__ Wada1, const float* __restrict__ Wada2,
    float* __restrict__ out)
{
    int li = blockIdx.y;
    const float* W = (li < NLAYER) ? (Wada1 + (size_t)li * HDIM * HDIM)
                                   : (Wada2 + (size_t)(li - NLAYER) * HDIM * HDIM);
    gemv8_core(tvec, W, nullptr, out + (size_t)li * BATCH * HDIM,
               HDIM, HDIM, 0, blockIdx.x);
}

// ---------------- rmsnorm (fp32 out) + optional fused zero of aux buffer ----------------
__global__ void __launch_bounds__(256) rmsnorm_kernel(
    const float* __restrict__ x, const float* __restrict__ w,
    const float* __restrict__ ada, float* __restrict__ out,
    float* __restrict__ zeroBuf, int zeroN)
{
    int row = blockIdx.x;
    int b = row / SEQ;
    const float* xr = x + (size_t)row * HDIM;
    __shared__ float red8[8];
    float s = 0.f;
    for (int i = threadIdx.x; i < HDIM; i += 256) {
        float v = xr[i];
        s += v * v;
    }
    float tot = block_sum256(s, red8);
    float r = rsqrtf(tot * (1.f / HDIM) + 1e-6f);
    for (int i = threadIdx.x; i < HDIM; i += 256) {
        float gmul = w[i];
        if (ada) gmul *= (1.f + ada[b * HDIM + i]);
        out[(size_t)row * HDIM + i] = xr[i] * r * gmul;
    }
    if (zeroBuf) {
        float4 z = make_float4(0.f, 0.f, 0.f, 0.f);
        for (int i = threadIdx.x; i < (zeroN >> 2); i += 256)
            *(float4*)(zeroBuf + (size_t)row * zeroN + (i << 2)) = z;
    }
}

// ---------------- softmax (zero-pads [TTOT, TPAD)) + fused zero of pao slice ----------------
__global__ void __launch_bounds__(256) softmax_kernel(float* __restrict__ paoZero)
{
    int row = blockIdx.x;
    float* p = g_sc + (size_t)row * TPAD;
    __shared__ float red8[8];
    float mx = -1e30f;
    for (int i = threadIdx.x; i < TTOT; i += 256) mx = fmaxf(mx, p[i]);
    float m = block_max256(mx, red8);
    __syncthreads();
    float s = 0.f;
    for (int i = threadIdx.x; i < TTOT; i += 256) {
        float e = expf(p[i] - m);
        p[i] = e;
        s += e;
    }
    float tot = block_sum256(s, red8);
    float inv = 1.f / tot;
    for (int i = threadIdx.x; i < TTOT; i += 256) p[i] *= inv;
    if (threadIdx.x < TPAD - TTOT) p[TTOT + threadIdx.x] = 0.f;
    paoZero[(size_t)row * 256 + threadIdx.x] = 0.f;
}

// ---------------- host ----------------
static inline dim3 gemm_grid(int M, int N) { return dim3((N + 63) / 64, (M + 63) / 64); }

extern "C" void kernel_launch(void* const* d_in, const int* in_sizes, int n_in,
                              void* d_out, int out_size)
{
    const float* x_t      = (const float*)d_in[0];
    const float* timestep = (const float*)d_in[1];
    const void*  mask     = d_in[2];
    const float* kvc      = (const float*)d_in[3];
    const float* Wa_in    = (const float*)d_in[4];
    const float* ba_in    = (const float*)d_in[5];
    const float* Wt_in    = (const float*)d_in[6];
    const float* bt_in    = (const float*)d_in[7];
    const float* Wt_out   = (const float*)d_in[8];
    const float* bt_out   = (const float*)d_in[9];
    const float* Wq       = (const float*)d_in[10];
    const float* Wk       = (const float*)d_in[11];
    const float* Wv       = (const float*)d_in[12];
    const float* Wo       = (const float*)d_in[13];
    const float* Wg       = (const float*)d_in[14];
    const float* Wu       = (const float*)d_in[15];
    const float* Wd       = (const float*)d_in[16];
    const float* n1_w     = (const float*)d_in[17];
    const float* n2_w     = (const float*)d_in[18];
    const float* Wada1    = (const float*)d_in[19];
    const float* Wada2    = (const float*)d_in[20];
    const float* nf_w     = (const float*)d_in[21];
    const float* Wa_out   = (const float*)d_in[22];
    const float* ba_out   = (const float*)d_in[23];

    cudaFuncSetAttribute(mma_gemm_kernel,
                         cudaFuncAttributeMaxDynamicSharedMemorySize, SMEM_GEMM_BYTES);
    cudaFuncSetAttribute(qkv_kernel,
                         cudaFuncAttributeMaxDynamicSharedMemorySize, SMEM_GEMM_BYTES);
    cudaFuncSetAttribute(attn_scores_kernel,
                         cudaFuncAttributeMaxDynamicSharedMemorySize, SMEM_ATTN_BYTES);
    cudaFuncSetAttribute(attn_pv_kernel,
                         cudaFuncAttributeMaxDynamicSharedMemorySize, SMEM_ATTN_BYTES);

    void* p;
    cudaGetSymbolAddress(&p, g_x);      float* px    = (float*)p;
    cudaGetSymbolAddress(&p, g_h);      float* ph    = (float*)p;
    cudaGetSymbolAddress(&p, g_temb);   float* ptemb = (float*)p;
    cudaGetSymbolAddress(&p, g_t1);     float* pt1   = (float*)p;
    cudaGetSymbolAddress(&p, g_tv);     float* ptv   = (float*)p;
    cudaGetSymbolAddress(&p, g_adaAll); float* padaA = (float*)p;
    cudaGetSymbolAddress(&p, g_qkv);    float* pqkv  = (float*)p;
    cudaGetSymbolAddress(&p, g_vt);     float* pvt   = (float*)p;
    cudaGetSymbolAddress(&p, g_ao);     float* pao   = (float*)p;
    cudaGetSymbolAddress(&p, g_gg);     float* pg    = (float*)p;
    cudaGetSymbolAddress(&p, g_uu);     float* pu    = (float*)p;

    prep_kernel<<<16, 512>>>(mask, timestep);

    gemv8_kernel<<<16, 256>>>(ptemb, Wt_in, bt_in, pt1, HDIM, HDIM, 1);
    gemv8_kernel<<<16, 256>>>(pt1, Wt_out, bt_out, ptv, HDIM, HDIM, 1);
    adaall_kernel<<<dim3(16, 2 * NLAYER), 256>>>(ptv, Wada1, Wada2, padaA);

    sgemm_kernel<<<gemm_grid(MTOK, HDIM), 256>>>(x_t, Wa_in, px, ba_in,
                                                 MTOK, HDIM, ADIM, ADIM, 0);

    for (int l = 0; l < NLAYER; l++) {
        const float* wq = Wq + (size_t)l * HDIM * (NHEAD * HEADD);
        const float* wk = Wk + (size_t)l * HDIM * HEADD;
        const float* wv = Wv + (size_t)l * HDIM * HEADD;
        const float* wo = Wo + (size_t)l * (NHEAD * HEADD) * HDIM;
        const float* wg = Wg + (size_t)l * HDIM * MLPD;
        const float* wu = Wu + (size_t)l * HDIM * MLPD;
        const float* wd = Wd + (size_t)l * MLPD * HDIM;
        const float* w1 = n1_w + (size_t)l * HDIM;
        const float* w2 = n2_w + (size_t)l * HDIM;
        const float* ada1 = padaA + (size_t)l * BATCH * HDIM;
        const float* ada2 = padaA + (size_t)(NLAYER + l) * BATCH * HDIM;

        // pre-attn norm + fused zero of qkv
        rmsnorm_kernel<<<MTOK, 256>>>(px, w1, ada1, ph, pqkv, QKVW);

        qkv_kernel<<<dim3(20, 7, 2), 256, SMEM_GEMM_BYTES>>>(ph, wq, wk, wv, pqkv);
        ropevtrans_kernel<<<1728 + 1800, 256>>>(pqkv, kvc, l, pvt);

        attn_scores_kernel<<<dim3(7, 7, 8), 256, SMEM_ATTN_BYTES>>>(pqkv, kvc, l);
        softmax_kernel<<<BATCH * NHEAD * SEQ, 256>>>(pao);
        attn_pv_kernel<<<dim3(2, 7, 16), 256, SMEM_ATTN_BYTES>>>(pvt, pao);

        mma_gemm_kernel<<<dim3(8, 7, 4), 256, SMEM_GEMM_BYTES>>>(
            pao, wo, px, nullptr, MTOK, HDIM, NHEAD * HEADD, 1);

        rmsnorm_kernel<<<MTOK, 256>>>(px, w2, ada2, ph, nullptr, 0);

        mma_gemm_kernel<<<dim3(32, 7, 1), 256, SMEM_GEMM_BYTES>>>(
            ph, wg, pg, nullptr, MTOK, MLPD, HDIM, 0);
        mma_gemm_kernel<<<dim3(32, 7, 1), 256, SMEM_GEMM_BYTES>>>(
            ph, wu, pu, pg, MTOK, MLPD, HDIM, 2);
        mma_gemm_kernel<<<dim3(8, 7, 4), 256, SMEM_GEMM_BYTES>>>(
            pu, wd, px, nullptr, MTOK, HDIM, MLPD, 1);
    }

    rmsnorm_kernel<<<MTOK, 256>>>(px, nf_w, nullptr, ph, nullptr, 0);
    sgemm_kernel<<<gemm_grid(MTOK, ADIM), 256>>>(ph, Wa_out, (float*)d_out, ba_out,
                                                 MTOK, ADIM, HDIM, HDIM, 0);
}

// round 17
// speedup vs baseline: 1.0467x; 1.0311x over previous
#include <cuda_runtime.h>
#include <math.h>
#include <stdint.h>

// ---------------- problem dims ----------------
#define NLAYER 18
#define HDIM   1024
#define NHEAD  8
#define HEADD  256
#define MLPD   4096
#define BATCH  8
#define SEQ    50
#define PREF   800
#define ADIM   32
#define TTOT   850
#define TPAD   864
#define MTOK   400
#define QKVW   2560    // combined qkv row width: q[0,2048) k[2048,2304) v[2304,2560)

// ---------------- device scratch ----------------
__device__ float g_x[MTOK * HDIM];
__device__ float g_h[MTOK * HDIM];
__device__ float g_temb[BATCH * HDIM];
__device__ float g_t1[BATCH * HDIM];
__device__ float g_tv[BATCH * HDIM];
__device__ float g_adaAll[2 * NLAYER * BATCH * HDIM];
__device__ float g_qkv[MTOK * QKVW];
__device__ float g_sc[BATCH * NHEAD * SEQ * TPAD];
__device__ float g_vt[BATCH * HEADD * TPAD];
__device__ float g_ao[MTOK * NHEAD * HEADD];
__device__ float g_gg[MTOK * MLPD];
__device__ float g_uu[MTOK * MLPD];
__device__ int   g_plen[BATCH];
__device__ float g_biasPref[BATCH * PREF];

// ---------------- bf16 split helpers ----------------
__device__ __forceinline__ void split2(float lo, float hi, uint32_t& hw, uint32_t& lw) {
    asm("cvt.rn.bf16x2.f32 %0, %1, %2;" : "=r"(hw) : "f"(hi), "f"(lo));
    float hlo = __uint_as_float(hw << 16);
    float hhi = __uint_as_float(hw & 0xffff0000u);
    asm("cvt.rn.bf16x2.f32 %0, %1, %2;" : "=r"(lw) : "f"(hi - hhi), "f"(lo - hlo));
}
__device__ __forceinline__ void mma_bf16(
    float c[4], const uint32_t a[4], uint32_t b0, uint32_t b1)
{
    asm volatile(
        "mma.sync.aligned.m16n8k16.row.col.f32.bf16.bf16.f32 "
        "{%0,%1,%2,%3}, {%4,%5,%6,%7}, {%8,%9}, {%0,%1,%2,%3};"
        : "+f"(c[0]), "+f"(c[1]), "+f"(c[2]), "+f"(c[3])
        : "r"(a[0]), "r"(a[1]), "r"(a[2]), "r"(a[3]), "r"(b0), "r"(b1));
}
__device__ __forceinline__ float gelu_f(float x) {
    float t = tanhf(0.7978845608028654f * (x + 0.044715f * x * x * x));
    return 0.5f * x * (1.f + t);
}

// warp-shuffle block reductions (256 threads)
__device__ __forceinline__ float block_sum256(float v, float* red8) {
#pragma unroll
    for (int o = 16; o > 0; o >>= 1) v += __shfl_xor_sync(0xffffffffu, v, o);
    if ((threadIdx.x & 31) == 0) red8[threadIdx.x >> 5] = v;
    __syncthreads();
    float r = red8[0] + red8[1] + red8[2] + red8[3]
            + red8[4] + red8[5] + red8[6] + red8[7];
    return r;
}
__device__ __forceinline__ float block_max256(float v, float* red8) {
#pragma unroll
    for (int o = 16; o > 0; o >>= 1) v = fmaxf(v, __shfl_xor_sync(0xffffffffu, v, o));
    if ((threadIdx.x & 31) == 0) red8[threadIdx.x >> 5] = v;
    __syncthreads();
    float r = fmaxf(fmaxf(fmaxf(red8[0], red8[1]), fmaxf(red8[2], red8[3])),
                    fmaxf(fmaxf(red8[4], red8[5]), fmaxf(red8[6], red8[7])));
    return r;
}

#define PADA 20
#define PADB 136
#define ABUF (64 * PADA)
#define BBUF (16 * PADB)
#define BBUF2 (128 * PADA)
#define SMEM_GEMM_BYTES ((4 * ABUF + 4 * BBUF) * 4)
#define SMEM_ATTN_BYTES ((4 * ABUF + 4 * BBUF2) * 4)

// ============ split-bf16 (3-term) GEMM core, M64, split-K, double-buffered ============
// epiMode: 0 store, 1 accumulate, 2 gated gelu, 3 atomicAdd.
__device__ __forceinline__ void gemm_core(
    const float* __restrict__ A, const float* __restrict__ W,
    float* __restrict__ C, const float* __restrict__ Cg,
    int M, int NwW, int colBaseW, int Nout, int colBaseC,
    int Kstride, int kBase, int nChunks, int rowBase, int epiMode,
    uint32_t* dyn)
{
    uint32_t* AsH = dyn;
    uint32_t* AsL = dyn + 2 * ABUF;
    uint32_t* BsH = dyn + 4 * ABUF;
    uint32_t* BsL = dyn + 4 * ABUF + 2 * BBUF;

    const int tid  = threadIdx.x;
    const int lane = tid & 31;
    const int warp = tid >> 5;
    const int wm = (warp & 1) << 5;
    const int wn = (warp >> 1) << 5;

    const int aRow = tid >> 3;
    const int aK4  = (tid & 7) << 2;
    const int aKw  = (tid & 7) << 1;
    const int bKw  = tid >> 4;
    const int bN   = (tid & 15) << 3;

    float c[2][4][4];
#pragma unroll
    for (int i = 0; i < 2; i++)
#pragma unroll
        for (int j = 0; j < 4; j++)
#pragma unroll
            for (int r = 0; r < 4; r++) c[i][j][r] = 0.f;

    float4 pa[2], pb[4];
    auto loadg = [&](int k0) {
#pragma unroll
        for (int p = 0; p < 2; p++) {
            int gr = rowBase + aRow + (p << 5);
            pa[p] = make_float4(0.f, 0.f, 0.f, 0.f);
            if (gr < M) pa[p] = *(const float4*)(A + (size_t)gr * Kstride + k0 + aK4);
        }
        const float* br0 = W + (size_t)(k0 + 2 * bKw) * NwW + colBaseW + bN;
        pb[0] = *(const float4*)(br0);
        pb[1] = *(const float4*)(br0 + 4);
        pb[2] = *(const float4*)(br0 + NwW);
        pb[3] = *(const float4*)(br0 + NwW + 4);
    };
    auto storeb = [&](int buf) {
        uint32_t* aH = AsH + buf * ABUF;
        uint32_t* aL = AsL + buf * ABUF;
        uint32_t* bH = BsH + buf * BBUF;
        uint32_t* bL = BsL + buf * BBUF;
#pragma unroll
        for (int p = 0; p < 2; p++) {
            int r = aRow + (p << 5);
            uint32_t h0, l0, h1, l1;
            split2(pa[p].x, pa[p].y, h0, l0);
            split2(pa[p].z, pa[p].w, h1, l1);
            *(uint2*)(&aH[r * PADA + aKw]) = make_uint2(h0, h1);
            *(uint2*)(&aL[r * PADA + aKw]) = make_uint2(l0, l1);
        }
        uint32_t hw[8], lw[8];
        const float* p0 = (const float*)&pb[0];
        const float* p1 = (const float*)&pb[2];
#pragma unroll
        for (int j = 0; j < 8; j++) split2(p0[j], p1[j], hw[j], lw[j]);
        *(uint4*)(&bH[bKw * PADB + bN])     = make_uint4(hw[0], hw[1], hw[2], hw[3]);
        *(uint4*)(&bH[bKw * PADB + bN + 4]) = make_uint4(hw[4], hw[5], hw[6], hw[7]);
        *(uint4*)(&bL[bKw * PADB + bN])     = make_uint4(lw[0], lw[1], lw[2], lw[3]);
        *(uint4*)(&bL[bKw * PADB + bN + 4]) = make_uint4(lw[4], lw[5], lw[6], lw[7]);
    };

    loadg(kBase);
    storeb(0);
    __syncthreads();

    for (int i = 0; i < nChunks; i++) {
        const int cur = i & 1;
        const bool more = (i + 1 < nChunks);
        if (more) loadg(kBase + ((i + 1) << 5));

        uint32_t* aH = AsH + cur * ABUF;
        uint32_t* aL = AsL + cur * ABUF;
        uint32_t* bH = BsH + cur * BBUF;
        uint32_t* bL = BsL + cur * BBUF;
#pragma unroll
        for (int ks = 0; ks < 2; ks++) {
            const int kf = (ks << 3) + (lane & 3);
            uint32_t bh[4][2], bl[4][2];
#pragma unroll
            for (int nf = 0; nf < 4; nf++) {
                int n0 = wn + (nf << 3) + (lane >> 2);
                bh[nf][0] = bH[kf * PADB + n0];
                bh[nf][1] = bH[(kf + 4) * PADB + n0];
                bl[nf][0] = bL[kf * PADB + n0];
                bl[nf][1] = bL[(kf + 4) * PADB + n0];
            }
#pragma unroll
            for (int mf = 0; mf < 2; mf++) {
                int m0 = wm + (mf << 4) + (lane >> 2);
                uint32_t ah[4], al[4];
                ah[0] = aH[m0 * PADA + kf];
                ah[1] = aH[(m0 + 8) * PADA + kf];
                ah[2] = aH[m0 * PADA + kf + 4];
                ah[3] = aH[(m0 + 8) * PADA + kf + 4];
                al[0] = aL[m0 * PADA + kf];
                al[1] = aL[(m0 + 8) * PADA + kf];
                al[2] = aL[m0 * PADA + kf + 4];
                al[3] = aL[(m0 + 8) * PADA + kf + 4];
#pragma unroll
                for (int nf = 0; nf < 4; nf++) {
                    mma_bf16(c[mf][nf], al, bh[nf][0], bh[nf][1]);
                    mma_bf16(c[mf][nf], ah, bl[nf][0], bl[nf][1]);
                    mma_bf16(c[mf][nf], ah, bh[nf][0], bh[nf][1]);
                }
            }
        }
        if (more) storeb(cur ^ 1);
        __syncthreads();
    }

#pragma unroll
    for (int mf = 0; mf < 2; mf++) {
        int r0 = rowBase + wm + (mf << 4) + (lane >> 2);
#pragma unroll
        for (int nf = 0; nf < 4; nf++) {
            int cc = colBaseC + wn + (nf << 3) + ((lane & 3) << 1);
#pragma unroll
            for (int half = 0; half < 2; half++) {
                int rr = r0 + half * 8;
                if (rr >= M) continue;
                size_t off = (size_t)rr * Nout + cc;
                float2 v = make_float2(c[mf][nf][half * 2], c[mf][nf][half * 2 + 1]);
                if (epiMode == 3) {
                    atomicAdd(C + off, v.x);
                    atomicAdd(C + off + 1, v.y);
                    continue;
                }
                if (epiMode == 1) {
                    float2 old = *(float2*)(C + off);
                    v.x += old.x; v.y += old.y;
                } else if (epiMode == 2) {
                    float2 gg = *(const float2*)(Cg + off);
                    v.x *= gelu_f(gg.x); v.y *= gelu_f(gg.y);
                }
                *(float2*)(C + off) = v;
            }
        }
    }
}

__global__ void __launch_bounds__(256, 2) mma_gemm_kernel(
    const float* __restrict__ A, const float* __restrict__ W,
    float* __restrict__ C, const float* __restrict__ Cg,
    int M, int N, int K, int epiMode)
{
    extern __shared__ uint32_t dyn[];
    int splits = gridDim.z;
    int kLen = K / splits;
    int kBase = blockIdx.z * kLen;
    int em = (splits > 1) ? 3 : epiMode;
    gemm_core(A, W, C, Cg, M, N, blockIdx.x * 128, N, blockIdx.x * 128,
              K, kBase, kLen >> 5, blockIdx.y * 64, em, dyn);
}

// fused QKV into combined buffer: grid (20, 7, 2) split-K, atomicAdd into zeroed output
__global__ void __launch_bounds__(256, 2) qkv_kernel(
    const float* __restrict__ A,
    const float* __restrict__ Wq, const float* __restrict__ Wk, const float* __restrict__ Wv,
    float* __restrict__ qkv)
{
    extern __shared__ uint32_t dyn[];
    int bx = blockIdx.x;
    const float* W; int NwW, colBaseW, colBaseC;
    if (bx < 16)      { W = Wq; NwW = 2048; colBaseW = bx * 128;        colBaseC = bx * 128; }
    else if (bx < 18) { W = Wk; NwW = 256;  colBaseW = (bx - 16) * 128; colBaseC = 2048 + (bx - 16) * 128; }
    else              { W = Wv; NwW = 256;  colBaseW = (bx - 18) * 128; colBaseC = 2304 + (bx - 18) * 128; }
    int kBase = blockIdx.z << 9;
    gemm_core(A, W, qkv, nullptr, MTOK, NwW, colBaseW, QKVW, colBaseC,
              HDIM, kBase, 16, blockIdx.y * 64, 3, dyn);
}

// ============ attention scores, double-buffered ============
// grid (7, 7, 8). S = Q @ K^T / 16 + bias.
__global__ void __launch_bounds__(256, 2) attn_scores_kernel(
    const float* __restrict__ qkv, const float* __restrict__ kvc, int layer)
{
    extern __shared__ uint32_t dyn[];
    uint32_t* AsH = dyn;
    uint32_t* AsL = dyn + 2 * ABUF;
    uint32_t* BsH = dyn + 4 * ABUF;
    uint32_t* BsL = dyn + 4 * ABUF + 2 * BBUF2;

    const int tid  = threadIdx.x;
    const int lane = tid & 31;
    const int warp = tid >> 5;
    const int wm = (warp & 1) << 5;
    const int wn = (warp >> 1) << 5;
    const int b = blockIdx.z;
    const int rowBase = blockIdx.y * 64;
    const int colBase = blockIdx.x * 128;

    const float* Kc = kvc + ((size_t)(layer * 2) * BATCH + b) * (size_t)(PREF * HEADD);
    const float* Qb = qkv + (size_t)b * SEQ * QKVW;

    const int aRow = tid >> 3;
    const int aK4  = (tid & 7) << 2;
    const int aKw  = (tid & 7) << 1;

    float c[2][4][4];
#pragma unroll
    for (int i = 0; i < 2; i++)
#pragma unroll
        for (int j = 0; j < 4; j++)
#pragma unroll
            for (int r = 0; r < 4; r++) c[i][j][r] = 0.f;

    float4 pa[2], pb[4];
    auto loadg = [&](int k0) {
#pragma unroll
        for (int p = 0; p < 2; p++) {
            int gr = rowBase + aRow + (p << 5);
            pa[p] = make_float4(0.f, 0.f, 0.f, 0.f);
            if (gr < 400) {
                int s = gr >> 3, h = gr & 7;
                pa[p] = *(const float4*)(Qb + (size_t)s * QKVW + h * 256 + k0 + aK4);
            }
        }
#pragma unroll
        for (int p = 0; p < 4; p++) {
            int t = colBase + aRow + (p << 5);
            pb[p] = make_float4(0.f, 0.f, 0.f, 0.f);
            if (t < PREF)      pb[p] = *(const float4*)(Kc + (size_t)t * 256 + k0 + aK4);
            else if (t < TTOT) pb[p] = *(const float4*)(qkv + (size_t)(b * SEQ + t - PREF) * QKVW + 2048 + k0 + aK4);
        }
    };
    auto storeb = [&](int buf) {
        uint32_t* aH = AsH + buf * ABUF;
        uint32_t* aL = AsL + buf * ABUF;
        uint32_t* bH = BsH + buf * BBUF2;
        uint32_t* bL = BsL + buf * BBUF2;
#pragma unroll
        for (int p = 0; p < 2; p++) {
            int r = aRow + (p << 5);
            uint32_t h0, l0, h1, l1;
            split2(pa[p].x, pa[p].y, h0, l0);
            split2(pa[p].z, pa[p].w, h1, l1);
            *(uint2*)(&aH[r * PADA + aKw]) = make_uint2(h0, h1);
            *(uint2*)(&aL[r * PADA + aKw]) = make_uint2(l0, l1);
        }
#pragma unroll
        for (int p = 0; p < 4; p++) {
            int r = aRow + (p << 5);
            uint32_t h0, l0, h1, l1;
            split2(pb[p].x, pb[p].y, h0, l0);
            split2(pb[p].z, pb[p].w, h1, l1);
            *(uint2*)(&bH[r * PADA + aKw]) = make_uint2(h0, h1);
            *(uint2*)(&bL[r * PADA + aKw]) = make_uint2(l0, l1);
        }
    };

    loadg(0);
    storeb(0);
    __syncthreads();

    for (int i = 0; i < 8; i++) {
        const int cur = i & 1;
        const bool more = (i + 1 < 8);
        if (more) loadg((i + 1) << 5);

        uint32_t* aH = AsH + cur * ABUF;
        uint32_t* aL = AsL + cur * ABUF;
        uint32_t* bH = BsH + cur * BBUF2;
        uint32_t* bL = BsL + cur * BBUF2;
#pragma unroll
        for (int ks = 0; ks < 2; ks++) {
            const int kf = (ks << 3) + (lane & 3);
            uint32_t bh[4][2], bl[4][2];
#pragma unroll
            for (int nf = 0; nf < 4; nf++) {
                int n0 = wn + (nf << 3) + (lane >> 2);
                bh[nf][0] = bH[n0 * PADA + kf];
                bh[nf][1] = bH[n0 * PADA + kf + 4];
                bl[nf][0] = bL[n0 * PADA + kf];
                bl[nf][1] = bL[n0 * PADA + kf + 4];
            }
#pragma unroll
            for (int mf = 0; mf < 2; mf++) {
                int m0 = wm + (mf << 4) + (lane >> 2);
                uint32_t ah[4], al[4];
                ah[0] = aH[m0 * PADA + kf];
                ah[1] = aH[(m0 + 8) * PADA + kf];
                ah[2] = aH[m0 * PADA + kf + 4];
                ah[3] = aH[(m0 + 8) * PADA + kf + 4];
                al[0] = aL[m0 * PADA + kf];
                al[1] = aL[(m0 + 8) * PADA + kf];
                al[2] = aL[m0 * PADA + kf + 4];
                al[3] = aL[(m0 + 8) * PADA + kf + 4];
#pragma unroll
                for (int nf = 0; nf < 4; nf++) {
                    mma_bf16(c[mf][nf], al, bh[nf][0], bh[nf][1]);
                    mma_bf16(c[mf][nf], ah, bl[nf][0], bl[nf][1]);
                    mma_bf16(c[mf][nf], ah, bh[nf][0], bh[nf][1]);
                }
            }
        }
        if (more) storeb(cur ^ 1);
        __syncthreads();
    }

    const float scale = 0.0625f;
#pragma unroll
    for (int mf = 0; mf < 2; mf++) {
        int r0 = rowBase + wm + (mf << 4) + (lane >> 2);
#pragma unroll
        for (int nf = 0; nf < 4; nf++) {
            int t = colBase + wn + (nf << 3) + ((lane & 3) << 1);
            if (t >= TTOT) continue;
            float2 bias;
            bias.x = (t < PREF) ? g_biasPref[b * PREF + t] : 0.f;
            bias.y = (t + 1 < PREF) ? g_biasPref[b * PREF + t + 1] : 0.f;
#pragma unroll
            for (int half = 0; half < 2; half++) {
                int rr = r0 + half * 8;
                if (rr >= 400) continue;
                int h = rr & 7, s = rr >> 3;
                size_t off = ((size_t)(b * 8 + h) * SEQ + s) * TPAD + t;
                float2 v = make_float2(c[mf][nf][half * 2] * scale + bias.x,
                                       c[mf][nf][half * 2 + 1] * scale + bias.y);
                *(float2*)(g_sc + off) = v;
            }
        }
    }
}

// ============ attention PV, double-buffered, split-T 2 ============
// grid (2, 7, 16): z = b*2 + half. atomicAdd into zeroed out.
__global__ void __launch_bounds__(256, 2) attn_pv_kernel(
    const float* __restrict__ vt, float* __restrict__ out)
{
    extern __shared__ uint32_t dyn[];
    uint32_t* AsH = dyn;
    uint32_t* AsL = dyn + 2 * ABUF;
    uint32_t* BsH = dyn + 4 * ABUF;
    uint32_t* BsL = dyn + 4 * ABUF + 2 * BBUF2;

    const int tid  = threadIdx.x;
    const int lane = tid & 31;
    const int warp = tid >> 5;
    const int wm = (warp & 1) << 5;
    const int wn = (warp >> 1) << 5;
    const int bz = blockIdx.z;
    const int b = bz >> 1;
    const int zs = bz & 1;
    const int kBase = zs ? 448 : 0;
    const int nChunks = zs ? 13 : 14;
    const int rowBase = blockIdx.y * 64;
    const int colBase = blockIdx.x * 128;

    const float* Ab = g_sc + (size_t)b * 400 * TPAD;
    const float* Bb = vt + (size_t)b * HEADD * TPAD;

    const int aRow = tid >> 3;
    const int aK4  = (tid & 7) << 2;
    const int aKw  = (tid & 7) << 1;

    float c[2][4][4];
#pragma unroll
    for (int i = 0; i < 2; i++)
#pragma unroll
        for (int j = 0; j < 4; j++)
#pragma unroll
            for (int r = 0; r < 4; r++) c[i][j][r] = 0.f;

    float4 pa[2], pb[4];
    auto loadg = [&](int k0) {
#pragma unroll
        for (int p = 0; p < 2; p++) {
            int gr = rowBase + aRow + (p << 5);
            pa[p] = make_float4(0.f, 0.f, 0.f, 0.f);
            if (gr < 400) pa[p] = *(const float4*)(Ab + (size_t)gr * TPAD + k0 + aK4);
        }
#pragma unroll
        for (int p = 0; p < 4; p++) {
            int d = colBase + aRow + (p << 5);
            pb[p] = *(const float4*)(Bb + (size_t)d * TPAD + k0 + aK4);
        }
    };
    auto storeb = [&](int buf) {
        uint32_t* aH = AsH + buf * ABUF;
        uint32_t* aL = AsL + buf * ABUF;
        uint32_t* bH = BsH + buf * BBUF2;
        uint32_t* bL = BsL + buf * BBUF2;
#pragma unroll
        for (int p = 0; p < 2; p++) {
            int r = aRow + (p << 5);
            uint32_t h0, l0, h1, l1;
            split2(pa[p].x, pa[p].y, h0, l0);
            split2(pa[p].z, pa[p].w, h1, l1);
            *(uint2*)(&aH[r * PADA + aKw]) = make_uint2(h0, h1);
            *(uint2*)(&aL[r * PADA + aKw]) = make_uint2(l0, l1);
        }
#pragma unroll
        for (int p = 0; p < 4; p++) {
            int r = aRow + (p << 5);
            uint32_t h0, l0, h1, l1;
            split2(pb[p].x, pb[p].y, h0, l0);
            split2(pb[p].z, pb[p].w, h1, l1);
            *(uint2*)(&bH[r * PADA + aKw]) = make_uint2(h0, h1);
            *(uint2*)(&bL[r * PADA + aKw]) = make_uint2(l0, l1);
        }
    };

    loadg(kBase);
    storeb(0);
    __syncthreads();

    for (int i = 0; i < nChunks; i++) {
        const int cur = i & 1;
        const bool more = (i + 1 < nChunks);
        if (more) loadg(kBase + ((i + 1) << 5));

        uint32_t* aH = AsH + cur * ABUF;
        uint32_t* aL = AsL + cur * ABUF;
        uint32_t* bH = BsH + cur * BBUF2;
        uint32_t* bL = BsL + cur * BBUF2;
#pragma unroll
        for (int ks = 0; ks < 2; ks++) {
            const int kf = (ks << 3) + (lane & 3);
            uint32_t bh[4][2], bl[4][2];
#pragma unroll
            for (int nf = 0; nf < 4; nf++) {
                int n0 = wn + (nf << 3) + (lane >> 2);
                bh[nf][0] = bH[n0 * PADA + kf];
                bh[nf][1] = bH[n0 * PADA + kf + 4];
                bl[nf][0] = bL[n0 * PADA + kf];
                bl[nf][1] = bL[n0 * PADA + kf + 4];
            }
#pragma unroll
            for (int mf = 0; mf < 2; mf++) {
                int m0 = wm + (mf << 4) + (lane >> 2);
                uint32_t ah[4], al[4];
                ah[0] = aH[m0 * PADA + kf];
                ah[1] = aH[(m0 + 8) * PADA + kf];
                ah[2] = aH[m0 * PADA + kf + 4];
                ah[3] = aH[(m0 + 8) * PADA + kf + 4];
                al[0] = aL[m0 * PADA + kf];
                al[1] = aL[(m0 + 8) * PADA + kf];
                al[2] = aL[m0 * PADA + kf + 4];
                al[3] = aL[(m0 + 8) * PADA + kf + 4];
#pragma unroll
                for (int nf = 0; nf < 4; nf++) {
                    mma_bf16(c[mf][nf], al, bh[nf][0], bh[nf][1]);
                    mma_bf16(c[mf][nf], ah, bl[nf][0], bl[nf][1]);
                    mma_bf16(c[mf][nf], ah, bh[nf][0], bh[nf][1]);
                }
            }
        }
        if (more) storeb(cur ^ 1);
        __syncthreads();
    }

#pragma unroll
    for (int mf = 0; mf < 2; mf++) {
        int r0 = rowBase + wm + (mf << 4) + (lane >> 2);
#pragma unroll
        for (int nf = 0; nf < 4; nf++) {
            int d = colBase + wn + (nf << 3) + ((lane & 3) << 1);
#pragma unroll
            for (int half = 0; half < 2; half++) {
                int rr = r0 + half * 8;
                if (rr >= 400) continue;
                int h = rr / SEQ, s = rr % SEQ;
                size_t off = (((size_t)(b * SEQ + s)) * 8 + h) * 256 + d;
                atomicAdd(out + off,     c[mf][nf][half * 2]);
                atomicAdd(out + off + 1, c[mf][nf][half * 2 + 1]);
            }
        }
    }
}

// ---------------- fused rope (q,k) + V transpose ----------------
__global__ void ropevtrans_kernel(float* __restrict__ qkv,
                                  const float* __restrict__ kvc, int layer,
                                  float* __restrict__ vt)
{
    int bid = blockIdx.x;
    int tid = threadIdx.x;
    if (bid < 1728) {
        __shared__ float tile[32][33];
        int t0 = (bid % 27) * 32;
        int rest = bid / 27;
        int d0 = (rest & 7) * 32;
        int b = rest >> 3;
        int tx = tid & 31, ty = tid >> 5;
        const float* Vc = kvc + ((size_t)(layer * 2 + 1) * BATCH + b) * (size_t)(PREF * HEADD);
#pragma unroll
        for (int j = 0; j < 4; j++) {
            int t = t0 + ty + j * 8;
            float v = 0.f;
            if (t < PREF)      v = Vc[(size_t)t * 256 + d0 + tx];
            else if (t < TTOT) v = qkv[(size_t)(b * SEQ + t - PREF) * QKVW + 2304 + d0 + tx];
            tile[ty + j * 8][tx] = v;
        }
        __syncthreads();
#pragma unroll
        for (int j = 0; j < 4; j++) {
            int d = d0 + ty + j * 8;
            vt[((size_t)b * HEADD + d) * TPAD + t0 + tx] = tile[tx][ty + j * 8];
        }
    } else {
        int idx = (bid - 1728) * 256 + tid;
        if (idx >= MTOK * 9 * 128) return;
        int j = idx & 127;
        int rest = idx >> 7;
        int hh = rest % 9;
        int row = rest / 9;
        int b = row / SEQ, s = row % SEQ;
        float pos = (float)(g_plen[b] + s);
        float inv = powf(10000.f, -(float)j / 128.f);
        float fr = pos * inv;
        float sn, cs;
        sincosf(fr, &sn, &cs);
        float* p = qkv + (size_t)row * QKVW + ((hh < 8) ? hh * 256 : 2048);
        float x1 = p[j], x2 = p[j + 128];
        p[j]       = x1 * cs - x2 * sn;
        p[j + 128] = x2 * cs + x1 * sn;
    }
}

// ---------------- prep ----------------
__global__ void prep_kernel(const void* __restrict__ maskp,
                            const float* __restrict__ ts)
{
    int bb = blockIdx.x;
    if (bb < BATCH) {
        int b = bb;
        const int* mi = (const int*)maskp;
        const unsigned char* mu = (const unsigned char*)maskp;
        int w0 = mi[0];
        bool is_i32 = (w0 == 0 || w0 == 1);
        __shared__ int cnt;
        if (threadIdx.x == 0) cnt = 0;
        __syncthreads();
        int local = 0;
        for (int t = threadIdx.x; t < PREF; t += blockDim.x) {
            int m = is_i32 ? mi[b * PREF + t] : (int)mu[b * PREF + t];
            bool on = (m != 0);
            g_biasPref[b * PREF + t] = on ? 0.f : -1e9f;
            if (on) local++;
        }
        atomicAdd(&cnt, local);
        __syncthreads();
        if (threadIdx.x == 0) g_plen[b] = cnt;
    } else {
        int b = bb - BATCH;
        float tsb = ts[b];
        for (int i = threadIdx.x; i < 512; i += blockDim.x) {
            float frac = (float)i / 511.f;
            float period = 4e-3f * powf(1000.f, frac);
            float arg = (6.283185307179586f / period) * tsb;
            float sv, cv;
            sincosf(arg, &sv, &cv);
            g_temb[b * HDIM + i]       = sv;
            g_temb[b * HDIM + 512 + i] = cv;
        }
    }
}

// ---------------- SIMT SGEMM (small GEMMs only) ----------------
__global__ void __launch_bounds__(256) sgemm_kernel(
    const float* __restrict__ A, const float* __restrict__ W,
    float* __restrict__ C, const float* __restrict__ bias,
    int M, int N, int K, int lda, int accumulate)
{
    __shared__ float As[16][64];
    __shared__ float Bs[16][64];
    const int tid = threadIdx.x;
    const int tx = tid & 15;
    const int ty = tid >> 4;
    const int rowBase = blockIdx.y * 64;
    const int colBase = blockIdx.x * 64;

    const int lm  = tid >> 2;
    const int lk  = (tid & 3) << 2;
    const int lkr = tid >> 4;
    const int ln  = (tid & 15) << 2;

    float acc[4][4];
#pragma unroll
    for (int i = 0; i < 4; i++)
#pragma unroll
        for (int j = 0; j < 4; j++) acc[i][j] = 0.f;

    for (int k0 = 0; k0 < K; k0 += 16) {
        float4 av = make_float4(0.f, 0.f, 0.f, 0.f);
        int ar = rowBase + lm;
        if (ar < M) av = *(const float4*)(A + (size_t)ar * lda + (k0 + lk));
        As[lk + 0][lm] = av.x;
        As[lk + 1][lm] = av.y;
        As[lk + 2][lm] = av.z;
        As[lk + 3][lm] = av.w;

        float4 bv;
        int bn = colBase + ln;
        const float* wrow = W + (size_t)(k0 + lkr) * N;
        if (bn + 3 < N) {
            bv = *(const float4*)(wrow + bn);
        } else {
            bv.x = (bn + 0 < N) ? wrow[bn + 0] : 0.f;
            bv.y = (bn + 1 < N) ? wrow[bn + 1] : 0.f;
            bv.z = (bn + 2 < N) ? wrow[bn + 2] : 0.f;
            bv.w = (bn + 3 < N) ? wrow[bn + 3] : 0.f;
        }
        *(float4*)(&Bs[lkr][ln]) = bv;
        __syncthreads();

#pragma unroll
        for (int kk = 0; kk < 16; kk++) {
            float4 a = *(const float4*)(&As[kk][ty << 2]);
            float4 b = *(const float4*)(&Bs[kk][tx << 2]);
            acc[0][0] += a.x * b.x; acc[0][1] += a.x * b.y; acc[0][2] += a.x * b.z; acc[0][3] += a.x * b.w;
            acc[1][0] += a.y * b.x; acc[1][1] += a.y * b.y; acc[1][2] += a.y * b.z; acc[1][3] += a.y * b.w;
            acc[2][0] += a.z * b.x; acc[2][1] += a.z * b.y; acc[2][2] += a.z * b.z; acc[2][3] += a.z * b.w;
            acc[3][0] += a.w * b.x; acc[3][1] += a.w * b.y; acc[3][2] += a.w * b.z; acc[3][3] += a.w * b.w;
        }
        __syncthreads();
    }

#pragma unroll
    for (int i = 0; i < 4; i++) {
        int r = rowBase + (ty << 2) + i;
        if (r >= M) continue;
#pragma unroll
        for (int j = 0; j < 4; j++) {
            int cx = colBase + (tx << 2) + j;
            if (cx >= N) continue;
            float v = acc[i][j];
            if (bias) v += bias[cx];
            size_t off = (size_t)r * N + cx;
            if (accumulate) v += C[off];
            C[off] = v;
        }
    }
}

// ---------------- small-M (M<=8) GEMM core ----------------
__device__ __forceinline__ void gemv8_core(
    const float* __restrict__ A, const float* __restrict__ W,
    const float* __restrict__ bias, float* __restrict__ C,
    int N, int K, int act, int bx)
{
    __shared__ float a_s[8 * 1024];
    __shared__ float red[4 * 64 * 8];
    int tid = threadIdx.x;
    for (int e = tid; e < 8 * K; e += 256) a_s[e] = A[e];
    __syncthreads();

    int nl = tid & 63;
    int n  = bx * 64 + nl;
    int ks = tid >> 6;
    float acc[8];
#pragma unroll
    for (int m = 0; m < 8; m++) acc[m] = 0.f;

    int kc = K >> 2;
    if (n < N) {
        int kbeg = ks * kc;
#pragma unroll 4
        for (int k = 0; k < kc; k++) {
            float w = W[(size_t)(kbeg + k) * N + n];
#pragma unroll
            for (int m = 0; m < 8; m++) acc[m] += a_s[m * K + kbeg + k] * w;
        }
    }
#pragma unroll
    for (int m = 0; m < 8; m++) red[tid * 8 + m] = acc[m];
    __syncthreads();
    if (ks == 0 && n < N) {
#pragma unroll
        for (int m = 0; m < 8; m++) {
            float v = red[(0 * 64 + nl) * 8 + m] + red[(1 * 64 + nl) * 8 + m] +
                      red[(2 * 64 + nl) * 8 + m] + red[(3 * 64 + nl) * 8 + m];
            if (bias) v += bias[n];
            if (act == 1) v = v / (1.f + expf(-v));
            C[(size_t)m * N + n] = v;
        }
    }
}

__global__ void __launch_bounds__(256) gemv8_kernel(
    const float* __restrict__ A, const float* __restrict__ W,
    const float* __restrict__ bias, float* __restrict__ C,
    int N, int K, int act)
{
    gemv8_core(A, W, bias, C, N, K, act, blockIdx.x);
}

__global__ void __launch_bounds__(256) adaall_kernel(
    const float* __restrict__ tvec,
    const float* __restrict__ Wada1, const float* __restrict__ Wada2,
    float* __restrict__ out)
{
    int li = blockIdx.y;
    const float* W = (li < NLAYER) ? (Wada1 + (size_t)li * HDIM * HDIM)
                                   : (Wada2 + (size_t)(li - NLAYER) * HDIM * HDIM);
    gemv8_core(tvec, W, nullptr, out + (size_t)li * BATCH * HDIM,
               HDIM, HDIM, 0, blockIdx.x);
}

// ---------------- rmsnorm (fp32 out, float4) + optional fused zero ----------------
__global__ void __launch_bounds__(256) rmsnorm_kernel(
    const float* __restrict__ x, const float* __restrict__ w,
    const float* __restrict__ ada, float* __restrict__ out,
    float* __restrict__ zeroBuf, int zeroN)
{
    int row = blockIdx.x;
    int b = row / SEQ;
    const float* xr = x + (size_t)row * HDIM;
    __shared__ float red8[8];
    int i4 = threadIdx.x << 2;          // 256 threads x 4 = 1024
    float4 xv = *(const float4*)(xr + i4);
    float s = xv.x * xv.x + xv.y * xv.y + xv.z * xv.z + xv.w * xv.w;
    float tot = block_sum256(s, red8);
    float r = rsqrtf(tot * (1.f / HDIM) + 1e-6f);
    float4 wv = *(const float4*)(w + i4);
    if (ada) {
        float4 av = *(const float4*)(ada + b * HDIM + i4);
        wv.x *= (1.f + av.x); wv.y *= (1.f + av.y);
        wv.z *= (1.f + av.z); wv.w *= (1.f + av.w);
    }
    float4 ov = make_float4(xv.x * r * wv.x, xv.y * r * wv.y,
                            xv.z * r * wv.z, xv.w * r * wv.w);
    *(float4*)(out + (size_t)row * HDIM + i4) = ov;
    if (zeroBuf) {
        float4 z = make_float4(0.f, 0.f, 0.f, 0.f);
        for (int i = threadIdx.x; i < (zeroN >> 2); i += 256)
            *(float4*)(zeroBuf + (size_t)row * zeroN + (i << 2)) = z;
    }
}

// ---------------- fused final rmsnorm + output projection ----------------
// grid 400, 256 threads. out[row, 0:32] = rms(x[row]) * nf_w @ Wa_out + ba_out
__global__ void __launch_bounds__(256) finalout_kernel(
    const float* __restrict__ x, const float* __restrict__ nfw,
    const float* __restrict__ Wout, const float* __restrict__ bout,
    float* __restrict__ out)
{
    int row = blockIdx.x;
    __shared__ float hs[HDIM];
    __shared__ float red8[8];
    __shared__ float red2[8][32];
    int tid = threadIdx.x;
    int i4 = tid << 2;
    const float* xr = x + (size_t)row * HDIM;
    float4 xv = *(const float4*)(xr + i4);
    float s = xv.x * xv.x + xv.y * xv.y + xv.z * xv.z + xv.w * xv.w;
    float tot = block_sum256(s, red8);
    float r = rsqrtf(tot * (1.f / HDIM) + 1e-6f);
    float4 wv = *(const float4*)(nfw + i4);
    float4 hv = make_float4(xv.x * r * wv.x, xv.y * r * wv.y,
                            xv.z * r * wv.z, xv.w * r * wv.w);
    *(float4*)(hs + i4) = hv;
    __syncthreads();

    int col = tid & 31;
    int ks  = tid >> 5;                 // 8 k-slices of 128
    const float* hp = hs + ks * 128;
    const float* Wp = Wout + (size_t)(ks * 128) * ADIM + col;
    float acc = 0.f;
#pragma unroll 8
    for (int k = 0; k < 128; k++)
        acc += hp[k] * Wp[(size_t)k * ADIM];
    red2[ks][col] = acc;
    __syncthreads();
    if (ks == 0) {
        float v = red2[0][col] + red2[1][col] + red2[2][col] + red2[3][col]
                + red2[4][col] + red2[5][col] + red2[6][col] + red2[7][col]
                + bout[col];
        out[(size_t)row * ADIM + col] = v;
    }
}

// ---------------- softmax (zero-pads [TTOT, TPAD)) + fused zero of pao slice ----------------
__global__ void __launch_bounds__(256) softmax_kernel(float* __restrict__ paoZero)
{
    int row = blockIdx.x;
    float* p = g_sc + (size_t)row * TPAD;
    __shared__ float red8[8];
    float mx = -1e30f;
    for (int i = threadIdx.x; i < TTOT; i += 256) mx = fmaxf(mx, p[i]);
    float m = block_max256(mx, red8);
    __syncthreads();
    float s = 0.f;
    for (int i = threadIdx.x; i < TTOT; i += 256) {
        float e = expf(p[i] - m);
        p[i] = e;
        s += e;
    }
    float tot = block_sum256(s, red8);
    float inv = 1.f / tot;
    for (int i = threadIdx.x; i < TTOT; i += 256) p[i] *= inv;
    if (threadIdx.x < TPAD - TTOT) p[TTOT + threadIdx.x] = 0.f;
    paoZero[(size_t)row * 256 + threadIdx.x] = 0.f;
}

// ---------------- host ----------------
static inline dim3 gemm_grid(int M, int N) { return dim3((N + 63) / 64, (M + 63) / 64); }

extern "C" void kernel_launch(void* const* d_in, const int* in_sizes, int n_in,
                              void* d_out, int out_size)
{
    const float* x_t      = (const float*)d_in[0];
    const float* timestep = (const float*)d_in[1];
    const void*  mask     = d_in[2];
    const float* kvc      = (const float*)d_in[3];
    const float* Wa_in    = (const float*)d_in[4];
    const float* ba_in    = (const float*)d_in[5];
    const float* Wt_in    = (const float*)d_in[6];
    const float* bt_in    = (const float*)d_in[7];
    const float* Wt_out   = (const float*)d_in[8];
    const float* bt_out   = (const float*)d_in[9];
    const float* Wq       = (const float*)d_in[10];
    const float* Wk       = (const float*)d_in[11];
    const float* Wv       = (const float*)d_in[12];
    const float* Wo       = (const float*)d_in[13];
    const float* Wg       = (const float*)d_in[14];
    const float* Wu       = (const float*)d_in[15];
    const float* Wd       = (const float*)d_in[16];
    const float* n1_w     = (const float*)d_in[17];
    const float* n2_w     = (const float*)d_in[18];
    const float* Wada1    = (const float*)d_in[19];
    const float* Wada2    = (const float*)d_in[20];
    const float* nf_w     = (const float*)d_in[21];
    const float* Wa_out   = (const float*)d_in[22];
    const float* ba_out   = (const float*)d_in[23];

    cudaFuncSetAttribute(mma_gemm_kernel,
                         cudaFuncAttributeMaxDynamicSharedMemorySize, SMEM_GEMM_BYTES);
    cudaFuncSetAttribute(qkv_kernel,
                         cudaFuncAttributeMaxDynamicSharedMemorySize, SMEM_GEMM_BYTES);
    cudaFuncSetAttribute(attn_scores_kernel,
                         cudaFuncAttributeMaxDynamicSharedMemorySize, SMEM_ATTN_BYTES);
    cudaFuncSetAttribute(attn_pv_kernel,
                         cudaFuncAttributeMaxDynamicSharedMemorySize, SMEM_ATTN_BYTES);

    void* p;
    cudaGetSymbolAddress(&p, g_x);      float* px    = (float*)p;
    cudaGetSymbolAddress(&p, g_h);      float* ph    = (float*)p;
    cudaGetSymbolAddress(&p, g_temb);   float* ptemb = (float*)p;
    cudaGetSymbolAddress(&p, g_t1);     float* pt1   = (float*)p;
    cudaGetSymbolAddress(&p, g_tv);     float* ptv   = (float*)p;
    cudaGetSymbolAddress(&p, g_adaAll); float* padaA = (float*)p;
    cudaGetSymbolAddress(&p, g_qkv);    float* pqkv  = (float*)p;
    cudaGetSymbolAddress(&p, g_vt);     float* pvt   = (float*)p;
    cudaGetSymbolAddress(&p, g_ao);     float* pao   = (float*)p;
    cudaGetSymbolAddress(&p, g_gg);     float* pg    = (float*)p;
    cudaGetSymbolAddress(&p, g_uu);     float* pu    = (float*)p;

    prep_kernel<<<16, 512>>>(mask, timestep);

    gemv8_kernel<<<16, 256>>>(ptemb, Wt_in, bt_in, pt1, HDIM, HDIM, 1);
    gemv8_kernel<<<16, 256>>>(pt1, Wt_out, bt_out, ptv, HDIM, HDIM, 1);
    adaall_kernel<<<dim3(16, 2 * NLAYER), 256>>>(ptv, Wada1, Wada2, padaA);

    sgemm_kernel<<<gemm_grid(MTOK, HDIM), 256>>>(x_t, Wa_in, px, ba_in,
                                                 MTOK, HDIM, ADIM, ADIM, 0);

    for (int l = 0; l < NLAYER; l++) {
        const float* wq = Wq + (size_t)l * HDIM * (NHEAD * HEADD);
        const float* wk = Wk + (size_t)l * HDIM * HEADD;
        const float* wv = Wv + (size_t)l * HDIM * HEADD;
        const float* wo = Wo + (size_t)l * (NHEAD * HEADD) * HDIM;
        const float* wg = Wg + (size_t)l * HDIM * MLPD;
        const float* wu = Wu + (size_t)l * HDIM * MLPD;
        const float* wd = Wd + (size_t)l * MLPD * HDIM;
        const float* w1 = n1_w + (size_t)l * HDIM;
        const float* w2 = n2_w + (size_t)l * HDIM;
        const float* ada1 = padaA + (size_t)l * BATCH * HDIM;
        const float* ada2 = padaA + (size_t)(NLAYER + l) * BATCH * HDIM;

        // pre-attn norm + fused zero of qkv
        rmsnorm_kernel<<<MTOK, 256>>>(px, w1, ada1, ph, pqkv, QKVW);

        qkv_kernel<<<dim3(20, 7, 2), 256, SMEM_GEMM_BYTES>>>(ph, wq, wk, wv, pqkv);
        ropevtrans_kernel<<<1728 + 1800, 256>>>(pqkv, kvc, l, pvt);

        attn_scores_kernel<<<dim3(7, 7, 8), 256, SMEM_ATTN_BYTES>>>(pqkv, kvc, l);
        softmax_kernel<<<BATCH * NHEAD * SEQ, 256>>>(pao);
        attn_pv_kernel<<<dim3(2, 7, 16), 256, SMEM_ATTN_BYTES>>>(pvt, pao);

        mma_gemm_kernel<<<dim3(8, 7, 4), 256, SMEM_GEMM_BYTES>>>(
            pao, wo, px, nullptr, MTOK, HDIM, NHEAD * HEADD, 1);

        rmsnorm_kernel<<<MTOK, 256>>>(px, w2, ada2, ph, nullptr, 0);

        mma_gemm_kernel<<<dim3(32, 7, 1), 256, SMEM_GEMM_BYTES>>>(
            ph, wg, pg, nullptr, MTOK, MLPD, HDIM, 0);
        mma_gemm_kernel<<<dim3(32, 7, 1), 256, SMEM_GEMM_BYTES>>>(
            ph, wu, pu, pg, MTOK, MLPD, HDIM, 2);
        mma_gemm_kernel<<<dim3(8, 7, 4), 256, SMEM_GEMM_BYTES>>>(
            pu, wd, px, nullptr, MTOK, HDIM, MLPD, 1);
    }

    // fused final norm + projection
    finalout_kernel<<<MTOK, 256>>>(px, nf_w, Wa_out, ba_out, (float*)d_out);
}